// round 1
// baseline (speedup 1.0000x reference)
#include <cuda_runtime.h>
#include <cstdint>

// Problem constants (fixed by the dataset).
#define BB 4
#define NN 20000
#define EE 320000
#define CIN 32
#define HID 64
#define ROWS (BB*NN)        // 80000
#define ZC 256              // 4 gates * 64

// -------- scratch (static device globals; no allocation) --------
__device__ float g_Z[(size_t)ROWS * ZC];     // 82 MB: gate pre-activations (pre-agg)
__device__ float g_Y[(size_t)ROWS * CIN];    // 10 MB: Hn @ Wo
__device__ int   g_deg[NN];
__device__ int   g_off[NN + 1];
__device__ int   g_cursor[NN];
__device__ int   g_csr[EE];
__device__ float g_dinv1[NN];
__device__ float g_dinv2[NN];
__device__ float g_sumsq;
__device__ float g_gbias[ZC];                // bx_g + bh_g + b_g per feature

__device__ __forceinline__ float sigf(float x) {
    return 1.0f / (1.0f + __expf(-x));
}

// -------- K1: sum of squares of X --------
__global__ void k_sumsq(const float* __restrict__ X, int n4) {
    float s = 0.f;
    const float4* X4 = (const float4*)X;
    for (int i = blockIdx.x * blockDim.x + threadIdx.x; i < n4; i += gridDim.x * blockDim.x) {
        float4 v = X4[i];
        s = fmaf(v.x, v.x, s); s = fmaf(v.y, v.y, s);
        s = fmaf(v.z, v.z, s); s = fmaf(v.w, v.w, s);
    }
    for (int o = 16; o > 0; o >>= 1) s += __shfl_down_sync(0xffffffffu, s, o);
    __shared__ float ws[8];
    int wid = threadIdx.x >> 5, lane = threadIdx.x & 31;
    if (lane == 0) ws[wid] = s;
    __syncthreads();
    if (wid == 0) {
        s = (lane < (int)(blockDim.x >> 5)) ? ws[lane] : 0.f;
        for (int o = 4; o > 0; o >>= 1) s += __shfl_down_sync(0xffffffffu, s, o);
        if (lane == 0) atomicAdd(&g_sumsq, s);
    }
}

// -------- K2: combined gate biases --------
__global__ void k_gbias(const float* bxi, const float* bxf, const float* bxc, const float* bxo,
                        const float* bhi, const float* bhf, const float* bhc, const float* bho,
                        const float* bi,  const float* bf,  const float* bc,  const float* bo_) {
    int k = threadIdx.x;         // 0..255
    int g = k >> 6, h = k & 63;
    const float* bx = (g == 0) ? bxi : (g == 1) ? bxf : (g == 2) ? bxc : bxo;
    const float* bh = (g == 0) ? bhi : (g == 1) ? bhf : (g == 2) ? bhc : bho;
    const float* bg = (g == 0) ? bi  : (g == 1) ? bf  : (g == 2) ? bc  : bo_;
    g_gbias[k] = bx[h] + bh[h] + bg[h];
}

// -------- K3: in-degree histogram --------
__global__ void k_hist(const int* __restrict__ ei) {
    int e = blockIdx.x * blockDim.x + threadIdx.x;
    if (e < EE) atomicAdd(&g_deg[ei[EE + e]], 1);
}

// -------- K4: single-block exclusive scan + dinv --------
__global__ void k_scan() {
    const int C = (NN + 1023) / 1024;  // 20
    __shared__ int sm[1024];
    int tid = threadIdx.x;
    int base = tid * C;
    int sum = 0;
    for (int j = 0; j < C; j++) { int idx = base + j; if (idx < NN) sum += g_deg[idx]; }
    sm[tid] = sum;
    __syncthreads();
    for (int off = 1; off < 1024; off <<= 1) {
        int v = (tid >= off) ? sm[tid - off] : 0;
        __syncthreads();
        sm[tid] += v;
        __syncthreads();
    }
    int run = sm[tid] - sum;  // exclusive
    for (int j = 0; j < C; j++) {
        int idx = base + j;
        if (idx < NN) {
            int d = g_deg[idx];
            g_off[idx] = run;
            run += d;
            g_dinv1[idx] = rsqrtf((float)d + 1.0f);
            g_dinv2[idx] = rsqrtf((float)d + 2.0f);
        }
    }
    if (tid == 1023) g_off[NN] = run;
}

// -------- K5: CSR fill (counting-sort scatter) --------
__global__ void k_csr(const int* __restrict__ ei) {
    int e = blockIdx.x * blockDim.x + threadIdx.x;
    if (e < EE) {
        int s = ei[e], d = ei[EE + e];
        int pos = atomicAdd(&g_cursor[d], 1);
        g_csr[g_off[d] + pos] = s;
    }
}

// -------- K6: Z = (X/gn)@Wx_cat + H@Wh_cat  [80000 x 256] --------
__global__ __launch_bounds__(256) void k_gemm(
    const float* __restrict__ X, const float* __restrict__ H,
    const float* __restrict__ Wxi, const float* __restrict__ Wxf,
    const float* __restrict__ Wxc, const float* __restrict__ Wxo,
    const float* __restrict__ Whi, const float* __restrict__ Whf,
    const float* __restrict__ Whc, const float* __restrict__ Who) {
    __shared__ float As[64][96];   // 24 KB
    __shared__ float Ws[16][256];  // 16 KB
    float invgn = rsqrtf(g_sumsq * (1.0f / (float)(ROWS * CIN)));
    int row0 = blockIdx.x * 64;
    int tid = threadIdx.x;

    // load A tile: X part (64x32) then H part (64x64)
    for (int i = tid; i < 64 * 8; i += 256) {
        int r = i >> 3, c4 = i & 7;
        float4 v = *(const float4*)(X + (size_t)(row0 + r) * CIN + c4 * 4);
        *(float4*)&As[r][c4 * 4] = v;
    }
    for (int i = tid; i < 64 * 16; i += 256) {
        int r = i >> 4, c4 = i & 15;
        float4 v = *(const float4*)(H + (size_t)(row0 + r) * HID + c4 * 4);
        *(float4*)&As[r][32 + c4 * 4] = v;
    }

    float acc[8][8];
#pragma unroll
    for (int r = 0; r < 8; r++)
#pragma unroll
        for (int c = 0; c < 8; c++) acc[r][c] = 0.f;

    int ty = tid >> 5, tx = tid & 31;

    for (int kk = 0; kk < 96; kk += 16) {
        __syncthreads();
        // load weight chunk Ws[16][256]
        for (int i = tid; i < 16 * 64; i += 256) {
            int kc = i >> 6, j4 = i & 63;
            int c = kk + kc;
            int j = j4 * 4;
            int g = j >> 6, h = j & 63;
            float4 w;
            if (c < 32) {
                const float* Wp = (g == 0) ? Wxi : (g == 1) ? Wxf : (g == 2) ? Wxc : Wxo;
                w = *(const float4*)(Wp + c * HID + h);
                w.x *= invgn; w.y *= invgn; w.z *= invgn; w.w *= invgn;
            } else {
                const float* Wp = (g == 0) ? Whi : (g == 1) ? Whf : (g == 2) ? Whc : Who;
                w = *(const float4*)(Wp + (c - 32) * HID + h);
            }
            *(float4*)&Ws[kc][j] = w;
        }
        __syncthreads();
#pragma unroll
        for (int k = 0; k < 16; k++) {
            float xr[8];
#pragma unroll
            for (int r = 0; r < 8; r++) xr[r] = As[ty * 8 + r][kk + k];
            float4 w0 = *(const float4*)&Ws[k][tx * 8];
            float4 w1 = *(const float4*)&Ws[k][tx * 8 + 4];
            float wv[8] = {w0.x, w0.y, w0.z, w0.w, w1.x, w1.y, w1.z, w1.w};
#pragma unroll
            for (int r = 0; r < 8; r++)
#pragma unroll
                for (int c = 0; c < 8; c++)
                    acc[r][c] = fmaf(xr[r], wv[c], acc[r][c]);
        }
    }

#pragma unroll
    for (int r = 0; r < 8; r++) {
        size_t row = (size_t)(row0 + ty * 8 + r);
        float* zp = g_Z + row * ZC + tx * 8;
        float4 o0 = {acc[r][0], acc[r][1], acc[r][2], acc[r][3]};
        float4 o1 = {acc[r][4], acc[r][5], acc[r][6], acc[r][7]};
        *(float4*)zp = o0;
        *(float4*)(zp + 4) = o1;
    }
}

// -------- K7: edge aggregation (fill=2) + gates + Hn@Wo, one warp per (node,batch) --------
__global__ __launch_bounds__(256) void k_agg(
    const float* __restrict__ Cst,
    const float* __restrict__ wci, const float* __restrict__ wcf, const float* __restrict__ wco,
    const float* __restrict__ Wo) {
    __shared__ float Wos[HID * CIN];   // 8 KB
    __shared__ float pre[8][ZC];       // 8 KB
    __shared__ float hn[8][HID];       // 2 KB

    int tid = threadIdx.x;
    for (int i = tid; i < HID * CIN; i += 256) Wos[i] = Wo[i];
    __syncthreads();

    int wid = tid >> 5, lane = tid & 31;
    int w = blockIdx.x * 8 + wid;
    if (w >= ROWS) return;
    int n = w % NN;
    int b = w / NN;
    const float* Zb = g_Z + (size_t)b * NN * ZC;

    int e0 = g_off[n], e1 = g_off[n + 1];
    float di = g_dinv2[n];

    float a[8];
#pragma unroll
    for (int c = 0; c < 8; c++) a[c] = 0.f;

    int e = e0;
    for (; e + 1 < e1; e += 2) {
        int s0 = g_csr[e], s1 = g_csr[e + 1];
        float nm0 = di * g_dinv2[s0];
        float nm1 = di * g_dinv2[s1];
        const float* z0p = Zb + (size_t)s0 * ZC + lane * 8;
        const float* z1p = Zb + (size_t)s1 * ZC + lane * 8;
        float4 u0 = *(const float4*)z0p, u1 = *(const float4*)(z0p + 4);
        float4 v0 = *(const float4*)z1p, v1 = *(const float4*)(z1p + 4);
        a[0] = fmaf(u0.x, nm0, a[0]); a[1] = fmaf(u0.y, nm0, a[1]);
        a[2] = fmaf(u0.z, nm0, a[2]); a[3] = fmaf(u0.w, nm0, a[3]);
        a[4] = fmaf(u1.x, nm0, a[4]); a[5] = fmaf(u1.y, nm0, a[5]);
        a[6] = fmaf(u1.z, nm0, a[6]); a[7] = fmaf(u1.w, nm0, a[7]);
        a[0] = fmaf(v0.x, nm1, a[0]); a[1] = fmaf(v0.y, nm1, a[1]);
        a[2] = fmaf(v0.z, nm1, a[2]); a[3] = fmaf(v0.w, nm1, a[3]);
        a[4] = fmaf(v1.x, nm1, a[4]); a[5] = fmaf(v1.y, nm1, a[5]);
        a[6] = fmaf(v1.z, nm1, a[6]); a[7] = fmaf(v1.w, nm1, a[7]);
    }
    if (e < e1) {
        int s0 = g_csr[e];
        float nm0 = di * g_dinv2[s0];
        const float* z0p = Zb + (size_t)s0 * ZC + lane * 8;
        float4 u0 = *(const float4*)z0p, u1 = *(const float4*)(z0p + 4);
        a[0] = fmaf(u0.x, nm0, a[0]); a[1] = fmaf(u0.y, nm0, a[1]);
        a[2] = fmaf(u0.z, nm0, a[2]); a[3] = fmaf(u0.w, nm0, a[3]);
        a[4] = fmaf(u1.x, nm0, a[4]); a[5] = fmaf(u1.y, nm0, a[5]);
        a[6] = fmaf(u1.z, nm0, a[6]); a[7] = fmaf(u1.w, nm0, a[7]);
    }

    // self term (fill=2) + combined biases
    {
        float sw = 2.0f * di * di;
        const float* zs = Zb + (size_t)n * ZC + lane * 8;
        float4 u0 = *(const float4*)zs, u1 = *(const float4*)(zs + 4);
        const float* gb = g_gbias + lane * 8;
        float4 b0 = *(const float4*)gb, b1 = *(const float4*)(gb + 4);
        a[0] = fmaf(u0.x, sw, a[0]) + b0.x; a[1] = fmaf(u0.y, sw, a[1]) + b0.y;
        a[2] = fmaf(u0.z, sw, a[2]) + b0.z; a[3] = fmaf(u0.w, sw, a[3]) + b0.w;
        a[4] = fmaf(u1.x, sw, a[4]) + b1.x; a[5] = fmaf(u1.y, sw, a[5]) + b1.y;
        a[6] = fmaf(u1.z, sw, a[6]) + b1.z; a[7] = fmaf(u1.w, sw, a[7]) + b1.w;
    }
    float4 p0 = {a[0], a[1], a[2], a[3]};
    float4 p1 = {a[4], a[5], a[6], a[7]};
    *(float4*)&pre[wid][lane * 8] = p0;
    *(float4*)&pre[wid][lane * 8 + 4] = p1;
    __syncwarp();

    // gates: each lane handles h = lane, lane+32
    for (int hh = lane; hh < HID; hh += 32) {
        float cst = Cst[((size_t)b * NN + n) * HID + hh];
        float pi = pre[wid][hh];
        float pf = pre[wid][64 + hh];
        float pc = pre[wid][128 + hh];
        float po = pre[wid][192 + hh];
        float I = sigf(pi + wci[hh] * cst);
        float F = sigf(pf + wcf[hh] * cst);
        float T = tanhf(pc);
        float Cn = F * cst + I * T;
        float O = sigf(po + wco[hh] * Cn);
        hn[wid][hh] = O * tanhf(Cn);
    }
    __syncwarp();

    // Y[b,n,lane] = sum_i hn[i] * Wo[i][lane]
    float y = 0.f;
#pragma unroll 8
    for (int i = 0; i < HID; i++) y = fmaf(hn[wid][i], Wos[i * CIN + lane], y);
    g_Y[((size_t)b * NN + n) * CIN + lane] = y;
}

// -------- K8: output GCN (fill=1), one warp per (node,batch), lane = out channel --------
__global__ __launch_bounds__(256) void k_out(float* __restrict__ out, const float* __restrict__ bo) {
    int tid = threadIdx.x;
    int wid = tid >> 5, lane = tid & 31;
    int w = blockIdx.x * 8 + wid;
    if (w >= ROWS) return;
    int n = w % NN;
    int b = w / NN;
    const float* Yb = g_Y + (size_t)b * NN * CIN;

    int e0 = g_off[n], e1 = g_off[n + 1];
    float di = g_dinv1[n];
    float acc = 0.f;
    int e = e0;
    for (; e + 1 < e1; e += 2) {
        int s0 = g_csr[e], s1 = g_csr[e + 1];
        float nm0 = di * g_dinv1[s0];
        float nm1 = di * g_dinv1[s1];
        float y0 = Yb[(size_t)s0 * CIN + lane];
        float y1 = Yb[(size_t)s1 * CIN + lane];
        acc = fmaf(y0, nm0, acc);
        acc = fmaf(y1, nm1, acc);
    }
    if (e < e1) {
        int s0 = g_csr[e];
        acc = fmaf(Yb[(size_t)s0 * CIN + lane], di * g_dinv1[s0], acc);
    }
    acc = fmaf(Yb[(size_t)n * CIN + lane], di * di, acc);  // fill = 1
    out[((size_t)b * NN + n) * CIN + lane] = acc + bo[lane];
}

extern "C" void kernel_launch(void* const* d_in, const int* in_sizes, int n_in,
                              void* d_out, int out_size) {
    const float* X   = (const float*)d_in[0];
    const float* H   = (const float*)d_in[1];
    const float* Cst = (const float*)d_in[2];
    const int*   ei  = (const int*)d_in[3];
    const float* Wxi = (const float*)d_in[4];
    const float* bxi = (const float*)d_in[5];
    const float* Whi = (const float*)d_in[6];
    const float* bhi = (const float*)d_in[7];
    const float* Wxf = (const float*)d_in[8];
    const float* bxf = (const float*)d_in[9];
    const float* Whf = (const float*)d_in[10];
    const float* bhf = (const float*)d_in[11];
    const float* Wxc = (const float*)d_in[12];
    const float* bxc = (const float*)d_in[13];
    const float* Whc = (const float*)d_in[14];
    const float* bhc = (const float*)d_in[15];
    const float* Wxo = (const float*)d_in[16];
    const float* bxo = (const float*)d_in[17];
    const float* Who = (const float*)d_in[18];
    const float* bho = (const float*)d_in[19];
    const float* wci = (const float*)d_in[20];
    const float* wcf = (const float*)d_in[21];
    const float* wco = (const float*)d_in[22];
    const float* bi  = (const float*)d_in[23];
    const float* bf  = (const float*)d_in[24];
    const float* bc  = (const float*)d_in[25];
    const float* bo_ = (const float*)d_in[26];
    const float* Wo  = (const float*)d_in[27];
    const float* bo2 = (const float*)d_in[28];
    float* out = (float*)d_out;

    // zero the small accumulators (scratch Z/Y are fully overwritten)
    void *p_sumsq, *p_deg, *p_cursor;
    cudaGetSymbolAddress(&p_sumsq, g_sumsq);
    cudaGetSymbolAddress(&p_deg, g_deg);
    cudaGetSymbolAddress(&p_cursor, g_cursor);
    cudaMemsetAsync(p_sumsq, 0, sizeof(float));
    cudaMemsetAsync(p_deg, 0, NN * sizeof(int));
    cudaMemsetAsync(p_cursor, 0, NN * sizeof(int));

    k_sumsq<<<512, 256>>>(X, ROWS * CIN / 4);
    k_gbias<<<1, 256>>>(bxi, bxf, bxc, bxo, bhi, bhf, bhc, bho, bi, bf, bc, bo_);
    k_hist<<<(EE + 255) / 256, 256>>>(ei);
    k_scan<<<1, 1024>>>();
    k_csr<<<(EE + 255) / 256, 256>>>(ei);
    k_gemm<<<ROWS / 64, 256>>>(X, H, Wxi, Wxf, Wxc, Wxo, Whi, Whf, Whc, Who);
    k_agg<<<ROWS / 8, 256>>>(Cst, wci, wcf, wco, Wo);
    k_out<<<ROWS / 8, 256>>>(out, bo2);
}

// round 2
// speedup vs baseline: 1.1915x; 1.1915x over previous
#include <cuda_runtime.h>
#include <cuda_fp16.h>
#include <cstdint>

// Problem constants (fixed by the dataset).
#define BB 4
#define NN 20000
#define EE 320000
#define CIN 32
#define HID 64
#define ROWS (BB*NN)        // 80000
#define ZC 256              // 4 gates * 64
#define SCAN_GRID ((NN + 255) / 256)   // 79

// -------- scratch (static device globals; no allocation) --------
__device__ __half g_Z[(size_t)ROWS * ZC];    // 41 MB: gate pre-activations (pre-agg), fp16
__device__ __half g_Y[(size_t)ROWS * CIN];   // 5 MB: Hn @ Wo, fp16
__device__ int   g_deg[NN];
__device__ int   g_off[NN + 1];
__device__ int   g_bsum[SCAN_GRID];
__device__ int   g_cursor[NN];
__device__ int   g_csr[EE];
__device__ float g_dinv1[NN];
__device__ float g_dinv2[NN];
__device__ float g_sumsq;
__device__ float g_gbias[ZC];                // bx_g + bh_g + b_g per feature

__device__ __forceinline__ float sigf(float x) {
    return 1.0f / (1.0f + __expf(-x));
}

// -------- K1: sum of squares of X --------
__global__ void k_sumsq(const float* __restrict__ X, int n4) {
    float s = 0.f;
    const float4* X4 = (const float4*)X;
    for (int i = blockIdx.x * blockDim.x + threadIdx.x; i < n4; i += gridDim.x * blockDim.x) {
        float4 v = X4[i];
        s = fmaf(v.x, v.x, s); s = fmaf(v.y, v.y, s);
        s = fmaf(v.z, v.z, s); s = fmaf(v.w, v.w, s);
    }
    for (int o = 16; o > 0; o >>= 1) s += __shfl_down_sync(0xffffffffu, s, o);
    __shared__ float ws[8];
    int wid = threadIdx.x >> 5, lane = threadIdx.x & 31;
    if (lane == 0) ws[wid] = s;
    __syncthreads();
    if (wid == 0) {
        s = (lane < (int)(blockDim.x >> 5)) ? ws[lane] : 0.f;
        for (int o = 4; o > 0; o >>= 1) s += __shfl_down_sync(0xffffffffu, s, o);
        if (lane == 0) atomicAdd(&g_sumsq, s);
    }
}

// -------- K2: combined gate biases --------
__global__ void k_gbias(const float* bxi, const float* bxf, const float* bxc, const float* bxo,
                        const float* bhi, const float* bhf, const float* bhc, const float* bho,
                        const float* bi,  const float* bf,  const float* bc,  const float* bo_) {
    int k = threadIdx.x;         // 0..255
    int g = k >> 6, h = k & 63;
    const float* bx = (g == 0) ? bxi : (g == 1) ? bxf : (g == 2) ? bxc : bxo;
    const float* bh = (g == 0) ? bhi : (g == 1) ? bhf : (g == 2) ? bhc : bho;
    const float* bg = (g == 0) ? bi  : (g == 1) ? bf  : (g == 2) ? bc  : bo_;
    g_gbias[k] = bx[h] + bh[h] + bg[h];
}

// -------- K3: in-degree histogram --------
__global__ void k_hist(const int* __restrict__ ei) {
    int e = blockIdx.x * blockDim.x + threadIdx.x;
    if (e < EE) atomicAdd(&g_deg[ei[EE + e]], 1);
}

// -------- K4a: per-block degree sums --------
__global__ void k_scan_a() {
    __shared__ int sm[256];
    int i = blockIdx.x * 256 + threadIdx.x;
    int v = (i < NN) ? g_deg[i] : 0;
    sm[threadIdx.x] = v;
    __syncthreads();
    for (int off = 128; off > 0; off >>= 1) {
        if (threadIdx.x < off) sm[threadIdx.x] += sm[threadIdx.x + off];
        __syncthreads();
    }
    if (threadIdx.x == 0) g_bsum[blockIdx.x] = sm[0];
}

// -------- K4b: scan the 79 block sums (exclusive, in place) --------
__global__ void k_scan_b() {
    __shared__ int sm[128];
    int t = threadIdx.x;
    int v = (t < SCAN_GRID) ? g_bsum[t] : 0;
    sm[t] = v;
    __syncthreads();
    for (int off = 1; off < 128; off <<= 1) {
        int u = (t >= off) ? sm[t - off] : 0;
        __syncthreads();
        sm[t] += u;
        __syncthreads();
    }
    if (t < SCAN_GRID) g_bsum[t] = sm[t] - v;   // exclusive
    if (t == 0) g_off[NN] = EE;
}

// -------- K4c: local exclusive scan + global offset, dinv --------
__global__ void k_scan_c() {
    __shared__ int sm[256];
    int i = blockIdx.x * 256 + threadIdx.x;
    int t = threadIdx.x;
    int d = (i < NN) ? g_deg[i] : 0;
    sm[t] = d;
    __syncthreads();
    for (int off = 1; off < 256; off <<= 1) {
        int u = (t >= off) ? sm[t - off] : 0;
        __syncthreads();
        sm[t] += u;
        __syncthreads();
    }
    if (i < NN) {
        g_off[i] = g_bsum[blockIdx.x] + sm[t] - d;   // exclusive
        g_dinv1[i] = rsqrtf((float)d + 1.0f);
        g_dinv2[i] = rsqrtf((float)d + 2.0f);
    }
}

// -------- K5: CSR fill (counting-sort scatter) --------
__global__ void k_csr(const int* __restrict__ ei) {
    int e = blockIdx.x * blockDim.x + threadIdx.x;
    if (e < EE) {
        int s = ei[e], d = ei[EE + e];
        int pos = atomicAdd(&g_cursor[d], 1);
        g_csr[g_off[d] + pos] = s;
    }
}

// -------- K6: Z = (X/gn)@Wx_cat + H@Wh_cat  [80000 x 256], fp16 out --------
__global__ __launch_bounds__(256) void k_gemm(
    const float* __restrict__ X, const float* __restrict__ H,
    const float* __restrict__ Wxi, const float* __restrict__ Wxf,
    const float* __restrict__ Wxc, const float* __restrict__ Wxo,
    const float* __restrict__ Whi, const float* __restrict__ Whf,
    const float* __restrict__ Whc, const float* __restrict__ Who) {
    __shared__ float As[64][96];   // 24 KB
    __shared__ float Ws[16][256];  // 16 KB
    float invgn = rsqrtf(g_sumsq * (1.0f / (float)(ROWS * CIN)));
    int row0 = blockIdx.x * 64;
    int tid = threadIdx.x;

    // load A tile: X part (64x32) then H part (64x64)
    for (int i = tid; i < 64 * 8; i += 256) {
        int r = i >> 3, c4 = i & 7;
        float4 v = *(const float4*)(X + (size_t)(row0 + r) * CIN + c4 * 4);
        *(float4*)&As[r][c4 * 4] = v;
    }
    for (int i = tid; i < 64 * 16; i += 256) {
        int r = i >> 4, c4 = i & 15;
        float4 v = *(const float4*)(H + (size_t)(row0 + r) * HID + c4 * 4);
        *(float4*)&As[r][32 + c4 * 4] = v;
    }

    float acc[8][8];
#pragma unroll
    for (int r = 0; r < 8; r++)
#pragma unroll
        for (int c = 0; c < 8; c++) acc[r][c] = 0.f;

    int ty = tid >> 5, tx = tid & 31;

    for (int kk = 0; kk < 96; kk += 16) {
        __syncthreads();
        // load weight chunk Ws[16][256]
        for (int i = tid; i < 16 * 64; i += 256) {
            int kc = i >> 6, j4 = i & 63;
            int c = kk + kc;
            int j = j4 * 4;
            int g = j >> 6, h = j & 63;
            float4 w;
            if (c < 32) {
                const float* Wp = (g == 0) ? Wxi : (g == 1) ? Wxf : (g == 2) ? Wxc : Wxo;
                w = *(const float4*)(Wp + c * HID + h);
                w.x *= invgn; w.y *= invgn; w.z *= invgn; w.w *= invgn;
            } else {
                const float* Wp = (g == 0) ? Whi : (g == 1) ? Whf : (g == 2) ? Whc : Who;
                w = *(const float4*)(Wp + (c - 32) * HID + h);
            }
            *(float4*)&Ws[kc][j] = w;
        }
        __syncthreads();
#pragma unroll
        for (int k = 0; k < 16; k++) {
            float xr[8];
#pragma unroll
            for (int r = 0; r < 8; r++) xr[r] = As[ty * 8 + r][kk + k];
            float4 w0 = *(const float4*)&Ws[k][tx * 8];
            float4 w1 = *(const float4*)&Ws[k][tx * 8 + 4];
            float wv[8] = {w0.x, w0.y, w0.z, w0.w, w1.x, w1.y, w1.z, w1.w};
#pragma unroll
            for (int r = 0; r < 8; r++)
#pragma unroll
                for (int c = 0; c < 8; c++)
                    acc[r][c] = fmaf(xr[r], wv[c], acc[r][c]);
        }
    }

#pragma unroll
    for (int r = 0; r < 8; r++) {
        size_t row = (size_t)(row0 + ty * 8 + r);
        __half* zp = g_Z + row * ZC + tx * 8;
        __half2 h0 = __floats2half2_rn(acc[r][0], acc[r][1]);
        __half2 h1 = __floats2half2_rn(acc[r][2], acc[r][3]);
        __half2 h2 = __floats2half2_rn(acc[r][4], acc[r][5]);
        __half2 h3 = __floats2half2_rn(acc[r][6], acc[r][7]);
        uint4 o;
        o.x = *(unsigned*)&h0; o.y = *(unsigned*)&h1;
        o.z = *(unsigned*)&h2; o.w = *(unsigned*)&h3;
        *(uint4*)zp = o;
    }
}

// accumulate 8 halves (one uint4) scaled by nm into a[8]
__device__ __forceinline__ void acc8(float* a, uint4 raw, float nm) {
    __half2 h0 = *(__half2*)&raw.x, h1 = *(__half2*)&raw.y;
    __half2 h2 = *(__half2*)&raw.z, h3 = *(__half2*)&raw.w;
    float2 f0 = __half22float2(h0), f1 = __half22float2(h1);
    float2 f2 = __half22float2(h2), f3 = __half22float2(h3);
    a[0] = fmaf(f0.x, nm, a[0]); a[1] = fmaf(f0.y, nm, a[1]);
    a[2] = fmaf(f1.x, nm, a[2]); a[3] = fmaf(f1.y, nm, a[3]);
    a[4] = fmaf(f2.x, nm, a[4]); a[5] = fmaf(f2.y, nm, a[5]);
    a[6] = fmaf(f3.x, nm, a[6]); a[7] = fmaf(f3.y, nm, a[7]);
}

// -------- K7: edge aggregation (fill=2) + gates + Hn@Wo, one warp per (node,batch) --------
__global__ __launch_bounds__(256) void k_agg(
    const float* __restrict__ Cst,
    const float* __restrict__ wci, const float* __restrict__ wcf, const float* __restrict__ wco,
    const float* __restrict__ Wo) {
    __shared__ float Wos[HID * CIN];   // 8 KB
    __shared__ float pre[8][ZC];       // 8 KB
    __shared__ float hn[8][HID];       // 2 KB

    int tid = threadIdx.x;
    for (int i = tid; i < HID * CIN; i += 256) Wos[i] = Wo[i];
    __syncthreads();

    int wid = tid >> 5, lane = tid & 31;
    int w = blockIdx.x * 8 + wid;
    if (w >= ROWS) return;
    int n = w % NN;
    int b = w / NN;
    const __half* Zb = g_Z + (size_t)b * NN * ZC;

    int e0 = g_off[n], e1 = g_off[n + 1];
    float di = g_dinv2[n];

    float a[8];
#pragma unroll
    for (int c = 0; c < 8; c++) a[c] = 0.f;

    int e = e0;
    for (; e + 1 < e1; e += 2) {
        int s0 = g_csr[e], s1 = g_csr[e + 1];
        float nm0 = di * g_dinv2[s0];
        float nm1 = di * g_dinv2[s1];
        uint4 r0 = *(const uint4*)(Zb + (size_t)s0 * ZC + lane * 8);
        uint4 r1 = *(const uint4*)(Zb + (size_t)s1 * ZC + lane * 8);
        acc8(a, r0, nm0);
        acc8(a, r1, nm1);
    }
    if (e < e1) {
        int s0 = g_csr[e];
        uint4 r0 = *(const uint4*)(Zb + (size_t)s0 * ZC + lane * 8);
        acc8(a, r0, di * g_dinv2[s0]);
    }

    // self term (fill=2) + combined biases
    {
        float sw = 2.0f * di * di;
        uint4 rs = *(const uint4*)(Zb + (size_t)n * ZC + lane * 8);
        acc8(a, rs, sw);
        const float* gb = g_gbias + lane * 8;
        float4 b0 = *(const float4*)gb, b1 = *(const float4*)(gb + 4);
        a[0] += b0.x; a[1] += b0.y; a[2] += b0.z; a[3] += b0.w;
        a[4] += b1.x; a[5] += b1.y; a[6] += b1.z; a[7] += b1.w;
    }
    float4 p0 = {a[0], a[1], a[2], a[3]};
    float4 p1 = {a[4], a[5], a[6], a[7]};
    *(float4*)&pre[wid][lane * 8] = p0;
    *(float4*)&pre[wid][lane * 8 + 4] = p1;
    __syncwarp();

    // gates: each lane handles h = lane, lane+32
    for (int hh = lane; hh < HID; hh += 32) {
        float cst = Cst[((size_t)b * NN + n) * HID + hh];
        float pi = pre[wid][hh];
        float pf = pre[wid][64 + hh];
        float pc = pre[wid][128 + hh];
        float po = pre[wid][192 + hh];
        float I = sigf(pi + wci[hh] * cst);
        float F = sigf(pf + wcf[hh] * cst);
        float T = tanhf(pc);
        float Cn = F * cst + I * T;
        float O = sigf(po + wco[hh] * Cn);
        hn[wid][hh] = O * tanhf(Cn);
    }
    __syncwarp();

    // Y[b,n,lane] = sum_i hn[i] * Wo[i][lane]
    float y = 0.f;
#pragma unroll 8
    for (int i = 0; i < HID; i++) y = fmaf(hn[wid][i], Wos[i * CIN + lane], y);
    g_Y[((size_t)b * NN + n) * CIN + lane] = __float2half_rn(y);
}

// -------- K8: output GCN (fill=1), one warp per (node,batch), lane = out channel --------
__global__ __launch_bounds__(256) void k_out(float* __restrict__ out, const float* __restrict__ bo) {
    int tid = threadIdx.x;
    int wid = tid >> 5, lane = tid & 31;
    int w = blockIdx.x * 8 + wid;
    if (w >= ROWS) return;
    int n = w % NN;
    int b = w / NN;
    const __half* Yb = g_Y + (size_t)b * NN * CIN;

    int e0 = g_off[n], e1 = g_off[n + 1];
    float di = g_dinv1[n];
    float acc = 0.f;
    int e = e0;
    for (; e + 1 < e1; e += 2) {
        int s0 = g_csr[e], s1 = g_csr[e + 1];
        float nm0 = di * g_dinv1[s0];
        float nm1 = di * g_dinv1[s1];
        float y0 = __half2float(Yb[(size_t)s0 * CIN + lane]);
        float y1 = __half2float(Yb[(size_t)s1 * CIN + lane]);
        acc = fmaf(y0, nm0, acc);
        acc = fmaf(y1, nm1, acc);
    }
    if (e < e1) {
        int s0 = g_csr[e];
        acc = fmaf(__half2float(Yb[(size_t)s0 * CIN + lane]), di * g_dinv1[s0], acc);
    }
    acc = fmaf(__half2float(Yb[(size_t)n * CIN + lane]), di * di, acc);  // fill = 1
    out[((size_t)b * NN + n) * CIN + lane] = acc + bo[lane];
}

extern "C" void kernel_launch(void* const* d_in, const int* in_sizes, int n_in,
                              void* d_out, int out_size) {
    const float* X   = (const float*)d_in[0];
    const float* H   = (const float*)d_in[1];
    const float* Cst = (const float*)d_in[2];
    const int*   ei  = (const int*)d_in[3];
    const float* Wxi = (const float*)d_in[4];
    const float* bxi = (const float*)d_in[5];
    const float* Whi = (const float*)d_in[6];
    const float* bhi = (const float*)d_in[7];
    const float* Wxf = (const float*)d_in[8];
    const float* bxf = (const float*)d_in[9];
    const float* Whf = (const float*)d_in[10];
    const float* bhf = (const float*)d_in[11];
    const float* Wxc = (const float*)d_in[12];
    const float* bxc = (const float*)d_in[13];
    const float* Whc = (const float*)d_in[14];
    const float* bhc = (const float*)d_in[15];
    const float* Wxo = (const float*)d_in[16];
    const float* bxo = (const float*)d_in[17];
    const float* Who = (const float*)d_in[18];
    const float* bho = (const float*)d_in[19];
    const float* wci = (const float*)d_in[20];
    const float* wcf = (const float*)d_in[21];
    const float* wco = (const float*)d_in[22];
    const float* bi  = (const float*)d_in[23];
    const float* bf  = (const float*)d_in[24];
    const float* bc  = (const float*)d_in[25];
    const float* bo_ = (const float*)d_in[26];
    const float* Wo  = (const float*)d_in[27];
    const float* bo2 = (const float*)d_in[28];
    float* out = (float*)d_out;

    // zero the small accumulators (scratch Z/Y are fully overwritten)
    void *p_sumsq, *p_deg, *p_cursor;
    cudaGetSymbolAddress(&p_sumsq, g_sumsq);
    cudaGetSymbolAddress(&p_deg, g_deg);
    cudaGetSymbolAddress(&p_cursor, g_cursor);
    cudaMemsetAsync(p_sumsq, 0, sizeof(float));
    cudaMemsetAsync(p_deg, 0, NN * sizeof(int));
    cudaMemsetAsync(p_cursor, 0, NN * sizeof(int));

    k_sumsq<<<512, 256>>>(X, ROWS * CIN / 4);
    k_gbias<<<1, 256>>>(bxi, bxf, bxc, bxo, bhi, bhf, bhc, bho, bi, bf, bc, bo_);
    k_hist<<<(EE + 255) / 256, 256>>>(ei);
    k_scan_a<<<SCAN_GRID, 256>>>();
    k_scan_b<<<1, 128>>>();
    k_scan_c<<<SCAN_GRID, 256>>>();
    k_csr<<<(EE + 255) / 256, 256>>>(ei);
    k_gemm<<<ROWS / 64, 256>>>(X, H, Wxi, Wxf, Wxc, Wxo, Whi, Whf, Whc, Who);
    k_agg<<<ROWS / 8, 256>>>(Cst, wci, wcf, wco, Wo);
    k_out<<<ROWS / 8, 256>>>(out, bo2);
}

// round 3
// speedup vs baseline: 1.2584x; 1.0562x over previous
#include <cuda_runtime.h>
#include <cuda_fp16.h>
#include <cstdint>

typedef unsigned long long ull;

// Problem constants (fixed by the dataset).
#define BB 4
#define NN 20000
#define EE 320000
#define CIN 32
#define HID 64
#define ROWS (BB*NN)        // 80000
#define ZC 256              // 4 gates * 64
#define XHC 96              // CIN + HID
#define SCAN_GRID ((NN + 255) / 256)   // 79

// -------- scratch (static device globals; no allocation) --------
__device__ __align__(16) __half g_XH[(size_t)ROWS * XHC];  // 15 MB: [Xn | H] fp16
__device__ __align__(16) float  g_U[(size_t)ROWS * XHC];   // 31 MB: agg + self, fp32
__device__ __align__(16) __half g_Z[(size_t)ROWS * ZC];    // 41 MB: gate pre-activations
__device__ __align__(16) __half g_Y[(size_t)ROWS * CIN];   // 5 MB: Hn @ Wo
__device__ int   g_deg[NN];
__device__ int   g_off[NN + 1];
__device__ int   g_bsum[SCAN_GRID];
__device__ int   g_cursor[NN];
__device__ int   g_csr[EE];
__device__ float g_dinv1[NN];
__device__ float g_dinv2[NN];
__device__ float g_sumsq;
__device__ float g_gbias[ZC];                // bx_g + bh_g + b_g per feature

__device__ __forceinline__ float sigf(float x) {
    return 1.0f / (1.0f + __expf(-x));
}

// ---- f32x2 packed math (sm_100+) ----
__device__ __forceinline__ ull pack_dup(float x) {
    ull r;
    asm("mov.b64 %0, {%1, %1};" : "=l"(r) : "f"(x));
    return r;
}
__device__ __forceinline__ ull ffma2(ull a, ull b, ull c) {
    ull d;
    asm("fma.rn.f32x2 %0, %1, %2, %3;" : "=l"(d) : "l"(a), "l"(b), "l"(c));
    return d;
}
__device__ __forceinline__ void unpack2(ull v, float& lo, float& hi) {
    asm("mov.b64 {%0, %1}, %2;" : "=f"(lo), "=f"(hi) : "l"(v));
}

// -------- K1: sum of squares of X --------
__global__ void k_sumsq(const float* __restrict__ X, int n4) {
    float s = 0.f;
    const float4* X4 = (const float4*)X;
    for (int i = blockIdx.x * blockDim.x + threadIdx.x; i < n4; i += gridDim.x * blockDim.x) {
        float4 v = X4[i];
        s = fmaf(v.x, v.x, s); s = fmaf(v.y, v.y, s);
        s = fmaf(v.z, v.z, s); s = fmaf(v.w, v.w, s);
    }
    for (int o = 16; o > 0; o >>= 1) s += __shfl_down_sync(0xffffffffu, s, o);
    __shared__ float ws[8];
    int wid = threadIdx.x >> 5, lane = threadIdx.x & 31;
    if (lane == 0) ws[wid] = s;
    __syncthreads();
    if (wid == 0) {
        s = (lane < (int)(blockDim.x >> 5)) ? ws[lane] : 0.f;
        for (int o = 4; o > 0; o >>= 1) s += __shfl_down_sync(0xffffffffu, s, o);
        if (lane == 0) atomicAdd(&g_sumsq, s);
    }
}

// -------- K2: combined gate biases --------
__global__ void k_gbias(const float* bxi, const float* bxf, const float* bxc, const float* bxo,
                        const float* bhi, const float* bhf, const float* bhc, const float* bho,
                        const float* bi,  const float* bf,  const float* bc,  const float* bo_) {
    int k = threadIdx.x;         // 0..255
    int g = k >> 6, h = k & 63;
    const float* bx = (g == 0) ? bxi : (g == 1) ? bxf : (g == 2) ? bxc : bxo;
    const float* bh = (g == 0) ? bhi : (g == 1) ? bhf : (g == 2) ? bhc : bho;
    const float* bg = (g == 0) ? bi  : (g == 1) ? bf  : (g == 2) ? bc  : bo_;
    g_gbias[k] = bx[h] + bh[h] + bg[h];
}

// -------- K3: in-degree histogram --------
__global__ void k_hist(const int* __restrict__ ei) {
    int e = blockIdx.x * blockDim.x + threadIdx.x;
    if (e < EE) atomicAdd(&g_deg[ei[EE + e]], 1);
}

// -------- K4a: per-block degree sums --------
__global__ void k_scan_a() {
    __shared__ int sm[256];
    int i = blockIdx.x * 256 + threadIdx.x;
    int v = (i < NN) ? g_deg[i] : 0;
    sm[threadIdx.x] = v;
    __syncthreads();
    for (int off = 128; off > 0; off >>= 1) {
        if (threadIdx.x < off) sm[threadIdx.x] += sm[threadIdx.x + off];
        __syncthreads();
    }
    if (threadIdx.x == 0) g_bsum[blockIdx.x] = sm[0];
}

// -------- K4b: scan the 79 block sums (exclusive, in place) --------
__global__ void k_scan_b() {
    __shared__ int sm[128];
    int t = threadIdx.x;
    int v = (t < SCAN_GRID) ? g_bsum[t] : 0;
    sm[t] = v;
    __syncthreads();
    for (int off = 1; off < 128; off <<= 1) {
        int u = (t >= off) ? sm[t - off] : 0;
        __syncthreads();
        sm[t] += u;
        __syncthreads();
    }
    if (t < SCAN_GRID) g_bsum[t] = sm[t] - v;   // exclusive
    if (t == 0) g_off[NN] = EE;
}

// -------- K4c: local exclusive scan + global offset, dinv --------
__global__ void k_scan_c() {
    __shared__ int sm[256];
    int i = blockIdx.x * 256 + threadIdx.x;
    int t = threadIdx.x;
    int d = (i < NN) ? g_deg[i] : 0;
    sm[t] = d;
    __syncthreads();
    for (int off = 1; off < 256; off <<= 1) {
        int u = (t >= off) ? sm[t - off] : 0;
        __syncthreads();
        sm[t] += u;
        __syncthreads();
    }
    if (i < NN) {
        g_off[i] = g_bsum[blockIdx.x] + sm[t] - d;   // exclusive
        g_dinv1[i] = rsqrtf((float)d + 1.0f);
        g_dinv2[i] = rsqrtf((float)d + 2.0f);
    }
}

// -------- K5: CSR fill (counting-sort scatter) --------
__global__ void k_csr(const int* __restrict__ ei) {
    int e = blockIdx.x * blockDim.x + threadIdx.x;
    if (e < EE) {
        int s = ei[e], d = ei[EE + e];
        int pos = atomicAdd(&g_cursor[d], 1);
        g_csr[g_off[d] + pos] = s;
    }
}

// -------- K6: pack XH = [X/gn | H] into fp16 --------
// one uint4 (8 halves) per thread-iter; 12 chunks per row
__global__ void k_pack(const float* __restrict__ X, const float* __restrict__ H) {
    float invgn = rsqrtf(g_sumsq * (1.0f / (float)(ROWS * CIN)));
    int total = ROWS * 12;
    for (int i = blockIdx.x * blockDim.x + threadIdx.x; i < total; i += gridDim.x * blockDim.x) {
        int row = i / 12, c = i % 12;
        float4 a, b;
        if (c < 4) {
            const float* xp = X + (size_t)row * CIN + c * 8;
            a = *(const float4*)xp;
            b = *(const float4*)(xp + 4);
            a.x *= invgn; a.y *= invgn; a.z *= invgn; a.w *= invgn;
            b.x *= invgn; b.y *= invgn; b.z *= invgn; b.w *= invgn;
        } else {
            const float* hp = H + (size_t)row * HID + (c - 4) * 8;
            a = *(const float4*)hp;
            b = *(const float4*)(hp + 4);
        }
        __half2 h0 = __floats2half2_rn(a.x, a.y);
        __half2 h1 = __floats2half2_rn(a.z, a.w);
        __half2 h2 = __floats2half2_rn(b.x, b.y);
        __half2 h3 = __floats2half2_rn(b.z, b.w);
        uint4 o;
        o.x = *(unsigned*)&h0; o.y = *(unsigned*)&h1;
        o.z = *(unsigned*)&h2; o.w = *(unsigned*)&h3;
        *(uint4*)(g_XH + (size_t)row * XHC + c * 8) = o;
    }
}

// accumulate 8 halves (one uint4) scaled by nm into a[8]
__device__ __forceinline__ void acc8(float* a, uint4 raw, float nm) {
    __half2 h0 = *(__half2*)&raw.x, h1 = *(__half2*)&raw.y;
    __half2 h2 = *(__half2*)&raw.z, h3 = *(__half2*)&raw.w;
    float2 f0 = __half22float2(h0), f1 = __half22float2(h1);
    float2 f2 = __half22float2(h2), f3 = __half22float2(h3);
    a[0] = fmaf(f0.x, nm, a[0]); a[1] = fmaf(f0.y, nm, a[1]);
    a[2] = fmaf(f1.x, nm, a[2]); a[3] = fmaf(f1.y, nm, a[3]);
    a[4] = fmaf(f2.x, nm, a[4]); a[5] = fmaf(f2.y, nm, a[5]);
    a[6] = fmaf(f3.x, nm, a[6]); a[7] = fmaf(f3.y, nm, a[7]);
}

// -------- K7: U = agg(XH) + 2*dinv2^2*XH  (fill=2 GCN aggregation on 96 features) --------
// one warp per (node,batch); 12 uint4 chunks per row; lanes 0-11 edge A, 12-23 edge B
__global__ __launch_bounds__(256) void k_aggxh() {
    int tid = threadIdx.x;
    int wid = tid >> 5, lane = tid & 31;
    int w = blockIdx.x * 8 + wid;
    if (w >= ROWS) return;
    int n = w % NN;
    int b = w / NN;
    const __half* XHb = g_XH + (size_t)b * NN * XHC;

    int e0 = g_off[n], e1 = g_off[n + 1];
    float di = g_dinv2[n];

    int half_ = (lane >= 12) ? 1 : 0;
    int chunk = lane - half_ * 12;       // 0..11 (lanes>=24: garbage, masked below)
    bool active = lane < 24;

    float a[8];
#pragma unroll
    for (int c = 0; c < 8; c++) a[c] = 0.f;

    for (int e = e0; e < e1; e += 2) {
        int idx = e + half_;
        if (active && idx < e1) {
            int s = g_csr[idx];
            float nm = di * g_dinv2[s];
            uint4 r = *(const uint4*)(XHb + (size_t)s * XHC + chunk * 8);
            acc8(a, r, nm);
        }
    }
    // lanes 0-11 += lanes 12-23
#pragma unroll
    for (int c = 0; c < 8; c++) a[c] += __shfl_down_sync(0xffffffffu, a[c], 12);

    if (lane < 12) {
        float sw = 2.0f * di * di;
        uint4 r = *(const uint4*)(XHb + (size_t)n * XHC + lane * 8);
        acc8(a, r, sw);
        float* up = g_U + (size_t)w * XHC + lane * 8;
        float4 o0 = {a[0], a[1], a[2], a[3]};
        float4 o1 = {a[4], a[5], a[6], a[7]};
        *(float4*)up = o0;
        *(float4*)(up + 4) = o1;
    }
}

// -------- K8: Z = U @ W_cat  [80000x96]@[96x256], fp16 out, f32x2 FMA --------
__global__ __launch_bounds__(256) void k_gemm(
    const float* __restrict__ Wxi, const float* __restrict__ Wxf,
    const float* __restrict__ Wxc, const float* __restrict__ Wxo,
    const float* __restrict__ Whi, const float* __restrict__ Whf,
    const float* __restrict__ Whc, const float* __restrict__ Who) {
    __shared__ float As[64][XHC];  // 24 KB
    __shared__ float Ws[16][ZC];   // 16 KB
    int row0 = blockIdx.x * 64;
    int tid = threadIdx.x;

    // load A tile (64 x 96 fp32)
    for (int i = tid; i < 64 * 24; i += 256) {
        int r = i / 24, c4 = i % 24;
        float4 v = *(const float4*)(g_U + (size_t)(row0 + r) * XHC + c4 * 4);
        *(float4*)&As[r][c4 * 4] = v;
    }

    ull acc2[8][4];
#pragma unroll
    for (int r = 0; r < 8; r++)
#pragma unroll
        for (int j = 0; j < 4; j++) acc2[r][j] = 0ull;

    int ty = tid >> 5, tx = tid & 31;

    for (int kk = 0; kk < XHC; kk += 16) {
        __syncthreads();
        // load weight chunk Ws[16][256]
        for (int i = tid; i < 16 * 64; i += 256) {
            int kc = i >> 6, j4 = i & 63;
            int c = kk + kc;
            int j = j4 * 4;
            int g = j >> 6, h = j & 63;
            float4 w;
            if (c < CIN) {
                const float* Wp = (g == 0) ? Wxi : (g == 1) ? Wxf : (g == 2) ? Wxc : Wxo;
                w = *(const float4*)(Wp + c * HID + h);
            } else {
                const float* Wp = (g == 0) ? Whi : (g == 1) ? Whf : (g == 2) ? Whc : Who;
                w = *(const float4*)(Wp + (c - CIN) * HID + h);
            }
            *(float4*)&Ws[kc][j] = w;
        }
        __syncthreads();
#pragma unroll
        for (int k = 0; k < 16; k++) {
            const ull* wp = (const ull*)&Ws[k][tx * 8];
            ull w2[4];
#pragma unroll
            for (int j = 0; j < 4; j++) w2[j] = wp[j];
#pragma unroll
            for (int r = 0; r < 8; r++) {
                ull x2 = pack_dup(As[ty * 8 + r][kk + k]);
#pragma unroll
                for (int j = 0; j < 4; j++)
                    acc2[r][j] = ffma2(x2, w2[j], acc2[r][j]);
            }
        }
    }

#pragma unroll
    for (int r = 0; r < 8; r++) {
        size_t row = (size_t)(row0 + ty * 8 + r);
        float lo0, hi0, lo1, hi1, lo2, hi2, lo3, hi3;
        unpack2(acc2[r][0], lo0, hi0);
        unpack2(acc2[r][1], lo1, hi1);
        unpack2(acc2[r][2], lo2, hi2);
        unpack2(acc2[r][3], lo3, hi3);
        __half2 h0 = __floats2half2_rn(lo0, hi0);
        __half2 h1 = __floats2half2_rn(lo1, hi1);
        __half2 h2 = __floats2half2_rn(lo2, hi2);
        __half2 h3 = __floats2half2_rn(lo3, hi3);
        uint4 o;
        o.x = *(unsigned*)&h0; o.y = *(unsigned*)&h1;
        o.z = *(unsigned*)&h2; o.w = *(unsigned*)&h3;
        *(uint4*)(g_Z + row * ZC + tx * 8) = o;
    }
}

// -------- K9: gates + peephole + Hn@Wo, one warp per (node,batch) --------
__global__ __launch_bounds__(256) void k_gates(
    const float* __restrict__ Cst,
    const float* __restrict__ wci, const float* __restrict__ wcf, const float* __restrict__ wco,
    const float* __restrict__ Wo) {
    __shared__ float Wos[HID * CIN];   // 8 KB
    __shared__ float gb[ZC];           // 1 KB
    __shared__ float pre[8][ZC];       // 8 KB
    __shared__ float hn[8][HID];       // 2 KB

    int tid = threadIdx.x;
    for (int i = tid; i < HID * CIN; i += 256) Wos[i] = Wo[i];
    if (tid < ZC) gb[tid] = g_gbias[tid];
    __syncthreads();

    int wid = tid >> 5, lane = tid & 31;
    int w = blockIdx.x * 8 + wid;
    if (w >= ROWS) return;
    int n = w % NN;
    int b = w / NN;

    // stage Z row (+bias) into smem as fp32
    {
        uint4 r = *(const uint4*)(g_Z + (size_t)w * ZC + lane * 8);
        __half2 h0 = *(__half2*)&r.x, h1 = *(__half2*)&r.y;
        __half2 h2 = *(__half2*)&r.z, h3 = *(__half2*)&r.w;
        float2 f0 = __half22float2(h0), f1 = __half22float2(h1);
        float2 f2 = __half22float2(h2), f3 = __half22float2(h3);
        int c0 = lane * 8;
        pre[wid][c0 + 0] = f0.x + gb[c0 + 0]; pre[wid][c0 + 1] = f0.y + gb[c0 + 1];
        pre[wid][c0 + 2] = f1.x + gb[c0 + 2]; pre[wid][c0 + 3] = f1.y + gb[c0 + 3];
        pre[wid][c0 + 4] = f2.x + gb[c0 + 4]; pre[wid][c0 + 5] = f2.y + gb[c0 + 5];
        pre[wid][c0 + 6] = f3.x + gb[c0 + 6]; pre[wid][c0 + 7] = f3.y + gb[c0 + 7];
    }
    __syncwarp();

    // gates: each lane handles h = lane, lane+32
    for (int hh = lane; hh < HID; hh += 32) {
        float cst = Cst[((size_t)b * NN + n) * HID + hh];
        float pi = pre[wid][hh];
        float pf = pre[wid][64 + hh];
        float pc = pre[wid][128 + hh];
        float po = pre[wid][192 + hh];
        float I = sigf(pi + wci[hh] * cst);
        float F = sigf(pf + wcf[hh] * cst);
        float T = tanhf(pc);
        float Cn = F * cst + I * T;
        float O = sigf(po + wco[hh] * Cn);
        hn[wid][hh] = O * tanhf(Cn);
    }
    __syncwarp();

    // Y[b,n,lane] = sum_i hn[i] * Wo[i][lane]
    float y = 0.f;
#pragma unroll 8
    for (int i = 0; i < HID; i++) y = fmaf(hn[wid][i], Wos[i * CIN + lane], y);
    g_Y[(size_t)w * CIN + lane] = __float2half_rn(y);
}

// -------- K10: output GCN (fill=1), one warp per (node,batch), lane = out channel --------
__global__ __launch_bounds__(256) void k_out(float* __restrict__ out, const float* __restrict__ bo) {
    int tid = threadIdx.x;
    int wid = tid >> 5, lane = tid & 31;
    int w = blockIdx.x * 8 + wid;
    if (w >= ROWS) return;
    int n = w % NN;
    int b = w / NN;
    const __half* Yb = g_Y + (size_t)b * NN * CIN;

    int e0 = g_off[n], e1 = g_off[n + 1];
    float di = g_dinv1[n];
    float acc = 0.f;
    int e = e0;
    for (; e + 1 < e1; e += 2) {
        int s0 = g_csr[e], s1 = g_csr[e + 1];
        float nm0 = di * g_dinv1[s0];
        float nm1 = di * g_dinv1[s1];
        float y0 = __half2float(Yb[(size_t)s0 * CIN + lane]);
        float y1 = __half2float(Yb[(size_t)s1 * CIN + lane]);
        acc = fmaf(y0, nm0, acc);
        acc = fmaf(y1, nm1, acc);
    }
    if (e < e1) {
        int s0 = g_csr[e];
        acc = fmaf(__half2float(Yb[(size_t)s0 * CIN + lane]), di * g_dinv1[s0], acc);
    }
    acc = fmaf(__half2float(Yb[(size_t)n * CIN + lane]), di * di, acc);  // fill = 1
    out[((size_t)b * NN + n) * CIN + lane] = acc + bo[lane];
}

extern "C" void kernel_launch(void* const* d_in, const int* in_sizes, int n_in,
                              void* d_out, int out_size) {
    const float* X   = (const float*)d_in[0];
    const float* H   = (const float*)d_in[1];
    const float* Cst = (const float*)d_in[2];
    const int*   ei  = (const int*)d_in[3];
    const float* Wxi = (const float*)d_in[4];
    const float* bxi = (const float*)d_in[5];
    const float* Whi = (const float*)d_in[6];
    const float* bhi = (const float*)d_in[7];
    const float* Wxf = (const float*)d_in[8];
    const float* bxf = (const float*)d_in[9];
    const float* Whf = (const float*)d_in[10];
    const float* bhf = (const float*)d_in[11];
    const float* Wxc = (const float*)d_in[12];
    const float* bxc = (const float*)d_in[13];
    const float* Whc = (const float*)d_in[14];
    const float* bhc = (const float*)d_in[15];
    const float* Wxo = (const float*)d_in[16];
    const float* bxo = (const float*)d_in[17];
    const float* Who = (const float*)d_in[18];
    const float* bho = (const float*)d_in[19];
    const float* wci = (const float*)d_in[20];
    const float* wcf = (const float*)d_in[21];
    const float* wco = (const float*)d_in[22];
    const float* bi  = (const float*)d_in[23];
    const float* bf  = (const float*)d_in[24];
    const float* bc  = (const float*)d_in[25];
    const float* bo_ = (const float*)d_in[26];
    const float* Wo  = (const float*)d_in[27];
    const float* bo2 = (const float*)d_in[28];
    float* out = (float*)d_out;

    // zero the small accumulators (scratch tensors are fully overwritten)
    void *p_sumsq, *p_deg, *p_cursor;
    cudaGetSymbolAddress(&p_sumsq, g_sumsq);
    cudaGetSymbolAddress(&p_deg, g_deg);
    cudaGetSymbolAddress(&p_cursor, g_cursor);
    cudaMemsetAsync(p_sumsq, 0, sizeof(float));
    cudaMemsetAsync(p_deg, 0, NN * sizeof(int));
    cudaMemsetAsync(p_cursor, 0, NN * sizeof(int));

    k_sumsq<<<512, 256>>>(X, ROWS * CIN / 4);
    k_gbias<<<1, 256>>>(bxi, bxf, bxc, bxo, bhi, bhf, bhc, bho, bi, bf, bc, bo_);
    k_hist<<<(EE + 255) / 256, 256>>>(ei);
    k_scan_a<<<SCAN_GRID, 256>>>();
    k_scan_b<<<1, 128>>>();
    k_scan_c<<<SCAN_GRID, 256>>>();
    k_csr<<<(EE + 255) / 256, 256>>>(ei);
    k_pack<<<592, 256>>>(X, H);
    k_aggxh<<<ROWS / 8, 256>>>();
    k_gemm<<<ROWS / 64, 256>>>(Wxi, Wxf, Wxc, Wxo, Whi, Whf, Whc, Who);
    k_gates<<<ROWS / 8, 256>>>(Cst, wci, wcf, wco, Wo);
    k_out<<<ROWS / 8, 256>>>(out, bo2);
}

// round 4
// speedup vs baseline: 1.9321x; 1.5353x over previous
#include <cuda_runtime.h>
#include <cuda_fp16.h>
#include <cstdint>

// Problem constants (fixed by the dataset).
#define BB 4
#define NN 20000
#define EE 320000
#define CIN 32
#define HID 64
#define ROWS (BB*NN)        // 80000
#define ZC 256              // 4 gates * 64
#define XHC 96              // CIN + HID
#define SCAN_GRID ((NN + 255) / 256)   // 79
#define GM_PAD 104          // padded row (halves) for conflict-free smem

// -------- scratch (static device globals; no allocation) --------
// Batch-interleaved layouts: [n][b][feat]
__device__ __align__(16) __half g_XH[(size_t)NN * BB * XHC];  // 15 MB: [n][b][96] fp16
__device__ __align__(16) __half g_U[(size_t)NN * BB * XHC];   // 15 MB: agg+self, fp16
__device__ __align__(16) __half g_Z[(size_t)ROWS * ZC];       // 41 MB: rows (n*4+b) x 256
__device__ __align__(16) __half g_Y[(size_t)NN * BB * CIN];   // 5 MB: [n][b][32]
__device__ __align__(16) __half g_Wt[ZC * XHC];               // 49 KB: Wt[n][k] fp16
__device__ int   g_deg[NN];
__device__ int   g_off[NN + 1];
__device__ int   g_bsum[SCAN_GRID];
__device__ int   g_cursor[NN];
__device__ int   g_csr[EE];
__device__ float g_dinv1[NN];
__device__ float g_dinv2[NN];
__device__ float g_sumsq;
__device__ float g_gbias[ZC];                // bx_g + bh_g + b_g per feature

__device__ __forceinline__ float sigf(float x) {
    return 1.0f / (1.0f + __expf(-x));
}

// -------- K1: sum of squares of X --------
__global__ void k_sumsq(const float* __restrict__ X, int n4) {
    float s = 0.f;
    const float4* X4 = (const float4*)X;
    for (int i = blockIdx.x * blockDim.x + threadIdx.x; i < n4; i += gridDim.x * blockDim.x) {
        float4 v = X4[i];
        s = fmaf(v.x, v.x, s); s = fmaf(v.y, v.y, s);
        s = fmaf(v.z, v.z, s); s = fmaf(v.w, v.w, s);
    }
    for (int o = 16; o > 0; o >>= 1) s += __shfl_down_sync(0xffffffffu, s, o);
    __shared__ float ws[8];
    int wid = threadIdx.x >> 5, lane = threadIdx.x & 31;
    if (lane == 0) ws[wid] = s;
    __syncthreads();
    if (wid == 0) {
        s = (lane < (int)(blockDim.x >> 5)) ? ws[lane] : 0.f;
        for (int o = 4; o > 0; o >>= 1) s += __shfl_down_sync(0xffffffffu, s, o);
        if (lane == 0) atomicAdd(&g_sumsq, s);
    }
}

// -------- K2: combined gate biases --------
__global__ void k_gbias(const float* bxi, const float* bxf, const float* bxc, const float* bxo,
                        const float* bhi, const float* bhf, const float* bhc, const float* bho,
                        const float* bi,  const float* bf,  const float* bc,  const float* bo_) {
    int k = threadIdx.x;         // 0..255
    int g = k >> 6, h = k & 63;
    const float* bx = (g == 0) ? bxi : (g == 1) ? bxf : (g == 2) ? bxc : bxo;
    const float* bh = (g == 0) ? bhi : (g == 1) ? bhf : (g == 2) ? bhc : bho;
    const float* bg = (g == 0) ? bi  : (g == 1) ? bf  : (g == 2) ? bc  : bo_;
    g_gbias[k] = bx[h] + bh[h] + bg[h];
}

// -------- K2b: pre-transpose all 8 weights to fp16 Wt[n][k] --------
__global__ void k_prepw(const float* Wxi, const float* Wxf, const float* Wxc, const float* Wxo,
                        const float* Whi, const float* Whf, const float* Whc, const float* Who) {
    int idx = blockIdx.x * 256 + threadIdx.x;
    if (idx >= ZC * XHC) return;
    int n = idx / XHC, k = idx % XHC;
    int g = n >> 6, h = n & 63;
    float w;
    if (k < CIN) {
        const float* Wp = (g == 0) ? Wxi : (g == 1) ? Wxf : (g == 2) ? Wxc : Wxo;
        w = Wp[k * HID + h];
    } else {
        const float* Wp = (g == 0) ? Whi : (g == 1) ? Whf : (g == 2) ? Whc : Who;
        w = Wp[(k - CIN) * HID + h];
    }
    g_Wt[n * XHC + k] = __float2half_rn(w);
}

// -------- K3: in-degree histogram --------
__global__ void k_hist(const int* __restrict__ ei) {
    int e = blockIdx.x * blockDim.x + threadIdx.x;
    if (e < EE) atomicAdd(&g_deg[ei[EE + e]], 1);
}

// -------- K4a: per-block degree sums --------
__global__ void k_scan_a() {
    __shared__ int sm[256];
    int i = blockIdx.x * 256 + threadIdx.x;
    int v = (i < NN) ? g_deg[i] : 0;
    sm[threadIdx.x] = v;
    __syncthreads();
    for (int off = 128; off > 0; off >>= 1) {
        if (threadIdx.x < off) sm[threadIdx.x] += sm[threadIdx.x + off];
        __syncthreads();
    }
    if (threadIdx.x == 0) g_bsum[blockIdx.x] = sm[0];
}

// -------- K4b: scan the 79 block sums (exclusive, in place) --------
__global__ void k_scan_b() {
    __shared__ int sm[128];
    int t = threadIdx.x;
    int v = (t < SCAN_GRID) ? g_bsum[t] : 0;
    sm[t] = v;
    __syncthreads();
    for (int off = 1; off < 128; off <<= 1) {
        int u = (t >= off) ? sm[t - off] : 0;
        __syncthreads();
        sm[t] += u;
        __syncthreads();
    }
    if (t < SCAN_GRID) g_bsum[t] = sm[t] - v;   // exclusive
    if (t == 0) g_off[NN] = EE;
}

// -------- K4c: local exclusive scan + global offset, dinv --------
__global__ void k_scan_c() {
    __shared__ int sm[256];
    int i = blockIdx.x * 256 + threadIdx.x;
    int t = threadIdx.x;
    int d = (i < NN) ? g_deg[i] : 0;
    sm[t] = d;
    __syncthreads();
    for (int off = 1; off < 256; off <<= 1) {
        int u = (t >= off) ? sm[t - off] : 0;
        __syncthreads();
        sm[t] += u;
        __syncthreads();
    }
    if (i < NN) {
        g_off[i] = g_bsum[blockIdx.x] + sm[t] - d;   // exclusive
        g_dinv1[i] = rsqrtf((float)d + 1.0f);
        g_dinv2[i] = rsqrtf((float)d + 2.0f);
    }
}

// -------- K5: CSR fill (counting-sort scatter) --------
__global__ void k_csr(const int* __restrict__ ei) {
    int e = blockIdx.x * blockDim.x + threadIdx.x;
    if (e < EE) {
        int s = ei[e], d = ei[EE + e];
        int pos = atomicAdd(&g_cursor[d], 1);
        g_csr[g_off[d] + pos] = s;
    }
}

// -------- K6: pack XH[n][b][96] = [X/gn | H] fp16 --------
// chunk = 8 halves (uint4); 48 chunks per node (4 batches x 12)
__global__ void k_pack(const float* __restrict__ X, const float* __restrict__ H) {
    float invgn = rsqrtf(g_sumsq * (1.0f / (float)(ROWS * CIN)));
    int total = NN * 48;
    for (int i = blockIdx.x * blockDim.x + threadIdx.x; i < total; i += gridDim.x * blockDim.x) {
        int n = i / 48, c = i % 48;
        int b = c / 12, fc = c % 12;
        float4 a, bb;
        if (fc < 4) {
            const float* xp = X + ((size_t)b * NN + n) * CIN + fc * 8;
            a = *(const float4*)xp;
            bb = *(const float4*)(xp + 4);
            a.x *= invgn; a.y *= invgn; a.z *= invgn; a.w *= invgn;
            bb.x *= invgn; bb.y *= invgn; bb.z *= invgn; bb.w *= invgn;
        } else {
            const float* hp = H + ((size_t)b * NN + n) * HID + (fc - 4) * 8;
            a = *(const float4*)hp;
            bb = *(const float4*)(hp + 4);
        }
        __half2 h0 = __floats2half2_rn(a.x, a.y);
        __half2 h1 = __floats2half2_rn(a.z, a.w);
        __half2 h2 = __floats2half2_rn(bb.x, bb.y);
        __half2 h3 = __floats2half2_rn(bb.z, bb.w);
        uint4 o;
        o.x = *(unsigned*)&h0; o.y = *(unsigned*)&h1;
        o.z = *(unsigned*)&h2; o.w = *(unsigned*)&h3;
        *(uint4*)(g_XH + (size_t)n * (BB * XHC) + c * 8) = o;
    }
}

// accumulate 8 halves (one uint4) scaled by nm into a[8]
__device__ __forceinline__ void acc8(float* a, uint4 raw, float nm) {
    __half2 h0 = *(__half2*)&raw.x, h1 = *(__half2*)&raw.y;
    __half2 h2 = *(__half2*)&raw.z, h3 = *(__half2*)&raw.w;
    float2 f0 = __half22float2(h0), f1 = __half22float2(h1);
    float2 f2 = __half22float2(h2), f3 = __half22float2(h3);
    a[0] = fmaf(f0.x, nm, a[0]); a[1] = fmaf(f0.y, nm, a[1]);
    a[2] = fmaf(f1.x, nm, a[2]); a[3] = fmaf(f1.y, nm, a[3]);
    a[4] = fmaf(f2.x, nm, a[4]); a[5] = fmaf(f2.y, nm, a[5]);
    a[6] = fmaf(f3.x, nm, a[6]); a[7] = fmaf(f3.y, nm, a[7]);
}

// -------- K7: U = agg(XH) + 2*dinv2^2*XH, all 4 batches per warp (fill=2) --------
// one warp per node; 48 chunks/node; lanes 0..23 own chunks {lane, lane+24}
__global__ __launch_bounds__(256) void k_aggxh() {
    int tid = threadIdx.x;
    int wid = tid >> 5, lane = tid & 31;
    int n = blockIdx.x * 8 + wid;
    if (n >= NN) return;

    int e0 = g_off[n], e1 = g_off[n + 1];
    float di = g_dinv2[n];
    bool active = lane < 24;
    int cA = lane, cB = lane + 24;

    float a[16];
#pragma unroll
    for (int c = 0; c < 16; c++) a[c] = 0.f;

    for (int e = e0; e < e1; e++) {
        int s = g_csr[e];
        float nm = di * g_dinv2[s];
        if (active) {
            const uint4* base = (const uint4*)(g_XH + (size_t)s * (BB * XHC));
            uint4 r0 = base[cA];
            uint4 r1 = base[cB];
            acc8(a, r0, nm);
            acc8(a + 8, r1, nm);
        }
    }
    if (active) {
        float sw = 2.0f * di * di;
        const uint4* base = (const uint4*)(g_XH + (size_t)n * (BB * XHC));
        acc8(a, base[cA], sw);
        acc8(a + 8, base[cB], sw);

        __half* up = g_U + (size_t)n * (BB * XHC);
        __half2 h0 = __floats2half2_rn(a[0], a[1]);
        __half2 h1 = __floats2half2_rn(a[2], a[3]);
        __half2 h2 = __floats2half2_rn(a[4], a[5]);
        __half2 h3 = __floats2half2_rn(a[6], a[7]);
        uint4 o0; o0.x = *(unsigned*)&h0; o0.y = *(unsigned*)&h1;
        o0.z = *(unsigned*)&h2; o0.w = *(unsigned*)&h3;
        ((uint4*)up)[cA] = o0;
        __half2 h4 = __floats2half2_rn(a[8], a[9]);
        __half2 h5 = __floats2half2_rn(a[10], a[11]);
        __half2 h6 = __floats2half2_rn(a[12], a[13]);
        __half2 h7 = __floats2half2_rn(a[14], a[15]);
        uint4 o1; o1.x = *(unsigned*)&h4; o1.y = *(unsigned*)&h5;
        o1.z = *(unsigned*)&h6; o1.w = *(unsigned*)&h7;
        ((uint4*)up)[cB] = o1;
    }
}

// -------- K8: Z = U @ Wt^T via mma.sync m16n8k16 (fp16 in, fp32 acc) --------
// block: 256 thr = 8 warps; tile 64 rows x 256 cols; K=96 (6 k-steps)
__device__ __forceinline__ void mma16816(float* c, unsigned a0, unsigned a1,
                                         unsigned a2, unsigned a3,
                                         unsigned b0, unsigned b1) {
    asm volatile(
        "mma.sync.aligned.m16n8k16.row.col.f32.f16.f16.f32 "
        "{%0,%1,%2,%3}, {%4,%5,%6,%7}, {%8,%9}, {%0,%1,%2,%3};"
        : "+f"(c[0]), "+f"(c[1]), "+f"(c[2]), "+f"(c[3])
        : "r"(a0), "r"(a1), "r"(a2), "r"(a3), "r"(b0), "r"(b1));
}

__global__ __launch_bounds__(256) void k_mma() {
    extern __shared__ __half smh[];
    __half* sW = smh;                     // 256 x GM_PAD
    __half* sA = smh + ZC * GM_PAD;       // 64 x GM_PAD
    int tid = threadIdx.x;
    int wid = tid >> 5, lane = tid & 31;

    // load Wt (256 x 96) -> sW
    for (int i = tid; i < ZC * 12; i += 256) {
        int nn = i / 12, c = i % 12;
        uint4 v = *(const uint4*)(g_Wt + nn * XHC + c * 8);
        *(uint4*)(sW + nn * GM_PAD + c * 8) = v;
    }
    // load A tile (64 x 96) -> sA
    int row0 = blockIdx.x * 64;
    for (int i = tid; i < 64 * 12; i += 256) {
        int r = i / 12, c = i % 12;
        uint4 v = *(const uint4*)(g_U + (size_t)(row0 + r) * XHC + c * 8);
        *(uint4*)(sA + r * GM_PAD + c * 8) = v;
    }
    __syncthreads();

    int warpRow = wid >> 1;      // 0..3 -> 16-row slab
    int warpCol = wid & 1;       // 0..1 -> 128-col slab
    int g = lane >> 2, tg = lane & 3;

    float acc[16][4];
#pragma unroll
    for (int j = 0; j < 16; j++)
#pragma unroll
        for (int q = 0; q < 4; q++) acc[j][q] = 0.f;

#pragma unroll
    for (int kt = 0; kt < 6; kt++) {
        int karow = kt * 16 + tg * 2;
        const __half* ar = sA + (warpRow * 16 + g) * GM_PAD;
        unsigned a0 = *(const unsigned*)(ar + karow);
        unsigned a1 = *(const unsigned*)(ar + 8 * GM_PAD + karow);
        unsigned a2 = *(const unsigned*)(ar + karow + 8);
        unsigned a3 = *(const unsigned*)(ar + 8 * GM_PAD + karow + 8);
#pragma unroll
        for (int j = 0; j < 16; j++) {
            int nn = warpCol * 128 + j * 8 + g;
            const __half* bp = sW + nn * GM_PAD + karow;
            unsigned b0 = *(const unsigned*)bp;
            unsigned b1 = *(const unsigned*)(bp + 8);
            mma16816(acc[j], a0, a1, a2, a3, b0, b1);
        }
    }

    // epilogue: fp32 -> fp16 store to g_Z
    int r = row0 + warpRow * 16 + g;
#pragma unroll
    for (int j = 0; j < 16; j++) {
        int nn = warpCol * 128 + j * 8 + tg * 2;
        __half2 h01 = __floats2half2_rn(acc[j][0], acc[j][1]);
        *(__half2*)(g_Z + (size_t)r * ZC + nn) = h01;
        __half2 h23 = __floats2half2_rn(acc[j][2], acc[j][3]);
        *(__half2*)(g_Z + (size_t)(r + 8) * ZC + nn) = h23;
    }
}

// -------- K9: gates + peephole + Hn@Wo, one warp per row (n*4+b) --------
__global__ __launch_bounds__(256) void k_gates(
    const float* __restrict__ Cst,
    const float* __restrict__ wci, const float* __restrict__ wcf, const float* __restrict__ wco,
    const float* __restrict__ Wo) {
    __shared__ float Wos[HID * CIN];   // 8 KB
    __shared__ float gb[ZC];           // 1 KB
    __shared__ float pre[8][ZC];       // 8 KB
    __shared__ float hn[8][HID];       // 2 KB

    int tid = threadIdx.x;
    for (int i = tid; i < HID * CIN; i += 256) Wos[i] = Wo[i];
    if (tid < ZC) gb[tid] = g_gbias[tid];
    __syncthreads();

    int wid = tid >> 5, lane = tid & 31;
    int w = blockIdx.x * 8 + wid;
    if (w >= ROWS) return;
    int n = w >> 2;        // rows are (n*4+b)
    int b = w & 3;

    // stage Z row (+bias) into smem as fp32
    {
        uint4 r = *(const uint4*)(g_Z + (size_t)w * ZC + lane * 8);
        __half2 h0 = *(__half2*)&r.x, h1 = *(__half2*)&r.y;
        __half2 h2 = *(__half2*)&r.z, h3 = *(__half2*)&r.w;
        float2 f0 = __half22float2(h0), f1 = __half22float2(h1);
        float2 f2 = __half22float2(h2), f3 = __half22float2(h3);
        int c0 = lane * 8;
        pre[wid][c0 + 0] = f0.x + gb[c0 + 0]; pre[wid][c0 + 1] = f0.y + gb[c0 + 1];
        pre[wid][c0 + 2] = f1.x + gb[c0 + 2]; pre[wid][c0 + 3] = f1.y + gb[c0 + 3];
        pre[wid][c0 + 4] = f2.x + gb[c0 + 4]; pre[wid][c0 + 5] = f2.y + gb[c0 + 5];
        pre[wid][c0 + 6] = f3.x + gb[c0 + 6]; pre[wid][c0 + 7] = f3.y + gb[c0 + 7];
    }
    __syncwarp();

    // gates: each lane handles h = lane, lane+32
    for (int hh = lane; hh < HID; hh += 32) {
        float cst = Cst[((size_t)b * NN + n) * HID + hh];
        float pi = pre[wid][hh];
        float pf = pre[wid][64 + hh];
        float pc = pre[wid][128 + hh];
        float po = pre[wid][192 + hh];
        float I = sigf(pi + wci[hh] * cst);
        float F = sigf(pf + wcf[hh] * cst);
        float T = tanhf(pc);
        float Cn = F * cst + I * T;
        float O = sigf(po + wco[hh] * Cn);
        hn[wid][hh] = O * tanhf(Cn);
    }
    __syncwarp();

    // Y[w][lane] = sum_i hn[i] * Wo[i][lane]   (layout = [n][b][32])
    float y = 0.f;
#pragma unroll 8
    for (int i = 0; i < HID; i++) y = fmaf(hn[wid][i], Wos[i * CIN + lane], y);
    g_Y[(size_t)w * CIN + lane] = __float2half_rn(y);
}

// -------- K10: output GCN (fill=1), one warp per node, all 4 batches --------
// Y row per node = 128 halves = 16 uint4 chunks; lanes 0..15 own one chunk each
__global__ __launch_bounds__(256) void k_out(float* __restrict__ out, const float* __restrict__ bo) {
    __shared__ float bos[CIN];
    int tid = threadIdx.x;
    if (tid < CIN) bos[tid] = bo[tid];
    __syncthreads();

    int wid = tid >> 5, lane = tid & 31;
    int n = blockIdx.x * 8 + wid;
    if (n >= NN) return;

    int e0 = g_off[n], e1 = g_off[n + 1];
    float di = g_dinv1[n];
    bool active = lane < 16;
    int chunk = lane;                 // b = chunk>>2, cols = (chunk&3)*8

    float a[8];
#pragma unroll
    for (int c = 0; c < 8; c++) a[c] = 0.f;

    for (int e = e0; e < e1; e++) {
        int s = g_csr[e];
        float nm = di * g_dinv1[s];
        if (active) {
            uint4 r = ((const uint4*)(g_Y + (size_t)s * (BB * CIN)))[chunk];
            acc8(a, r, nm);
        }
    }
    if (active) {
        uint4 r = ((const uint4*)(g_Y + (size_t)n * (BB * CIN)))[chunk];
        acc8(a, r, di * di);          // fill = 1 self term

        int b = chunk >> 2, colc = (chunk & 3) * 8;
        float* op = out + ((size_t)b * NN + n) * CIN + colc;
        float4 o0 = {a[0] + bos[colc + 0], a[1] + bos[colc + 1],
                     a[2] + bos[colc + 2], a[3] + bos[colc + 3]};
        float4 o1 = {a[4] + bos[colc + 4], a[5] + bos[colc + 5],
                     a[6] + bos[colc + 6], a[7] + bos[colc + 7]};
        *(float4*)op = o0;
        *(float4*)(op + 4) = o1;
    }
}

extern "C" void kernel_launch(void* const* d_in, const int* in_sizes, int n_in,
                              void* d_out, int out_size) {
    const float* X   = (const float*)d_in[0];
    const float* H   = (const float*)d_in[1];
    const float* Cst = (const float*)d_in[2];
    const int*   ei  = (const int*)d_in[3];
    const float* Wxi = (const float*)d_in[4];
    const float* bxi = (const float*)d_in[5];
    const float* Whi = (const float*)d_in[6];
    const float* bhi = (const float*)d_in[7];
    const float* Wxf = (const float*)d_in[8];
    const float* bxf = (const float*)d_in[9];
    const float* Whf = (const float*)d_in[10];
    const float* bhf = (const float*)d_in[11];
    const float* Wxc = (const float*)d_in[12];
    const float* bxc = (const float*)d_in[13];
    const float* Whc = (const float*)d_in[14];
    const float* bhc = (const float*)d_in[15];
    const float* Wxo = (const float*)d_in[16];
    const float* bxo = (const float*)d_in[17];
    const float* Who = (const float*)d_in[18];
    const float* bho = (const float*)d_in[19];
    const float* wci = (const float*)d_in[20];
    const float* wcf = (const float*)d_in[21];
    const float* wco = (const float*)d_in[22];
    const float* bi  = (const float*)d_in[23];
    const float* bf  = (const float*)d_in[24];
    const float* bc  = (const float*)d_in[25];
    const float* bo_ = (const float*)d_in[26];
    const float* Wo  = (const float*)d_in[27];
    const float* bo2 = (const float*)d_in[28];
    float* out = (float*)d_out;

    static bool attr_set = false;
    if (!attr_set) {
        cudaFuncSetAttribute(k_mma, cudaFuncAttributeMaxDynamicSharedMemorySize,
                             (ZC + 64) * GM_PAD * (int)sizeof(__half));
        attr_set = true;
    }

    // zero the small accumulators (scratch tensors are fully overwritten)
    void *p_sumsq, *p_deg, *p_cursor;
    cudaGetSymbolAddress(&p_sumsq, g_sumsq);
    cudaGetSymbolAddress(&p_deg, g_deg);
    cudaGetSymbolAddress(&p_cursor, g_cursor);
    cudaMemsetAsync(p_sumsq, 0, sizeof(float));
    cudaMemsetAsync(p_deg, 0, NN * sizeof(int));
    cudaMemsetAsync(p_cursor, 0, NN * sizeof(int));

    k_sumsq<<<512, 256>>>(X, ROWS * CIN / 4);
    k_gbias<<<1, 256>>>(bxi, bxf, bxc, bxo, bhi, bhf, bhc, bho, bi, bf, bc, bo_);
    k_prepw<<<(ZC * XHC + 255) / 256, 256>>>(Wxi, Wxf, Wxc, Wxo, Whi, Whf, Whc, Who);
    k_hist<<<(EE + 255) / 256, 256>>>(ei);
    k_scan_a<<<SCAN_GRID, 256>>>();
    k_scan_b<<<1, 128>>>();
    k_scan_c<<<SCAN_GRID, 256>>>();
    k_csr<<<(EE + 255) / 256, 256>>>(ei);
    k_pack<<<592, 256>>>(X, H);
    k_aggxh<<<(NN + 7) / 8, 256>>>();
    k_mma<<<ROWS / 64, 256, (ZC + 64) * GM_PAD * (int)sizeof(__half)>>>();
    k_gates<<<ROWS / 8, 256>>>(Cst, wci, wcf, wco, Wo);
    k_out<<<(NN + 7) / 8, 256>>>(out, bo2);
}

// round 5
// speedup vs baseline: 2.4480x; 1.2671x over previous
#include <cuda_runtime.h>
#include <cuda_fp16.h>
#include <cstdint>

// Problem constants (fixed by the dataset).
#define BB 4
#define NN 20000
#define EE 320000
#define CIN 32
#define HID 64
#define ROWS (BB*NN)        // 80000
#define ZC 256              // 4 gates * 64
#define XHC 96              // CIN + HID
#define SCAN_GRID ((NN + 255) / 256)   // 79
#define GM_PAD 104          // padded row (halves) for conflict-free smem
#define ZPAD 264            // sZ pitch in halves

// -------- scratch (static device globals; no allocation) --------
// Batch-interleaved layouts: [n][b][feat]
__device__ __align__(16) __half g_XH[(size_t)NN * BB * XHC];  // 15 MB
__device__ __align__(16) __half g_U[(size_t)NN * BB * XHC];   // 15 MB
__device__ __align__(16) __half g_Y[(size_t)NN * BB * CIN];   // 5 MB
__device__ __align__(16) __half g_Wt[ZC * XHC];               // 49 KB: Wt[n][k] fp16
__device__ int   g_deg[NN];
__device__ int   g_off[NN + 1];
__device__ int   g_bsum[SCAN_GRID];
__device__ int   g_cursor[NN];
__device__ int   g_csr[EE];
__device__ float g_dinv1[NN];
__device__ float g_dinv2[NN];
__device__ float g_sumsq;
__device__ float g_gbias[ZC];                // bx_g + bh_g + b_g per feature

__device__ __forceinline__ float sigf(float x) {
    return 1.0f / (1.0f + __expf(-x));
}
__device__ __forceinline__ float tanh_ap(float x) {
    float r;
    asm("tanh.approx.f32 %0, %1;" : "=f"(r) : "f"(x));
    return r;
}

// -------- K_setup: fused [sumsq | hist | gbias | prepw] via grid split --------
#define SETUP_SUMSQ_BLKS 512
#define SETUP_HIST_BLKS  (EE / 256)          // 1250
#define SETUP_GBIAS_BLK  (SETUP_SUMSQ_BLKS + SETUP_HIST_BLKS)  // 1762
#define SETUP_PREPW0     (SETUP_GBIAS_BLK + 1)                  // 1763
#define SETUP_PREPW_BLKS ((ZC * XHC + 255) / 256)               // 96
#define SETUP_GRID       (SETUP_PREPW0 + SETUP_PREPW_BLKS)      // 1859

__global__ __launch_bounds__(256) void k_setup(
    const float* __restrict__ X, const int* __restrict__ ei,
    const float* Wxi, const float* Wxf, const float* Wxc, const float* Wxo,
    const float* Whi, const float* Whf, const float* Whc, const float* Who,
    const float* bxi, const float* bxf, const float* bxc, const float* bxo,
    const float* bhi, const float* bhf, const float* bhc, const float* bho,
    const float* bi,  const float* bf,  const float* bc,  const float* bo_) {
    int bid = blockIdx.x, tid = threadIdx.x;
    if (bid < SETUP_SUMSQ_BLKS) {
        // sum of squares of X
        const int n4 = ROWS * CIN / 4;
        float s = 0.f;
        const float4* X4 = (const float4*)X;
        for (int i = bid * 256 + tid; i < n4; i += SETUP_SUMSQ_BLKS * 256) {
            float4 v = X4[i];
            s = fmaf(v.x, v.x, s); s = fmaf(v.y, v.y, s);
            s = fmaf(v.z, v.z, s); s = fmaf(v.w, v.w, s);
        }
        for (int o = 16; o > 0; o >>= 1) s += __shfl_down_sync(0xffffffffu, s, o);
        __shared__ float ws[8];
        int wid = tid >> 5, lane = tid & 31;
        if (lane == 0) ws[wid] = s;
        __syncthreads();
        if (wid == 0) {
            s = (lane < 8) ? ws[lane] : 0.f;
            for (int o = 4; o > 0; o >>= 1) s += __shfl_down_sync(0xffffffffu, s, o);
            if (lane == 0) atomicAdd(&g_sumsq, s);
        }
    } else if (bid < SETUP_GBIAS_BLK) {
        // degree histogram
        int e = (bid - SETUP_SUMSQ_BLKS) * 256 + tid;
        if (e < EE) atomicAdd(&g_deg[ei[EE + e]], 1);
    } else if (bid == SETUP_GBIAS_BLK) {
        // combined gate biases
        int k = tid, g = k >> 6, h = k & 63;
        const float* bx = (g == 0) ? bxi : (g == 1) ? bxf : (g == 2) ? bxc : bxo;
        const float* bh = (g == 0) ? bhi : (g == 1) ? bhf : (g == 2) ? bhc : bho;
        const float* bg = (g == 0) ? bi  : (g == 1) ? bf  : (g == 2) ? bc  : bo_;
        g_gbias[k] = bx[h] + bh[h] + bg[h];
    } else {
        // weight transpose to fp16 Wt[n][k]
        int idx = (bid - SETUP_PREPW0) * 256 + tid;
        if (idx < ZC * XHC) {
            int n = idx / XHC, k = idx % XHC;
            int g = n >> 6, h = n & 63;
            float w;
            if (k < CIN) {
                const float* Wp = (g == 0) ? Wxi : (g == 1) ? Wxf : (g == 2) ? Wxc : Wxo;
                w = Wp[k * HID + h];
            } else {
                const float* Wp = (g == 0) ? Whi : (g == 1) ? Whf : (g == 2) ? Whc : Who;
                w = Wp[(k - CIN) * HID + h];
            }
            g_Wt[n * XHC + k] = __float2half_rn(w);
        }
    }
}

// -------- K_scan_a: per-block degree sums --------
__global__ void k_scan_a() {
    __shared__ int sm[256];
    int i = blockIdx.x * 256 + threadIdx.x;
    int v = (i < NN) ? g_deg[i] : 0;
    sm[threadIdx.x] = v;
    __syncthreads();
    for (int off = 128; off > 0; off >>= 1) {
        if (threadIdx.x < off) sm[threadIdx.x] += sm[threadIdx.x + off];
        __syncthreads();
    }
    if (threadIdx.x == 0) g_bsum[blockIdx.x] = sm[0];
}

// -------- K_scan_b: scan the 79 block sums (exclusive, in place) --------
__global__ void k_scan_b() {
    __shared__ int sm[128];
    int t = threadIdx.x;
    int v = (t < SCAN_GRID) ? g_bsum[t] : 0;
    sm[t] = v;
    __syncthreads();
    for (int off = 1; off < 128; off <<= 1) {
        int u = (t >= off) ? sm[t - off] : 0;
        __syncthreads();
        sm[t] += u;
        __syncthreads();
    }
    if (t < SCAN_GRID) g_bsum[t] = sm[t] - v;   // exclusive
    if (t == 0) g_off[NN] = EE;
}

// -------- K_scan_c: local exclusive scan + dinv + cursor zero --------
__global__ void k_scan_c() {
    __shared__ int sm[256];
    int i = blockIdx.x * 256 + threadIdx.x;
    int t = threadIdx.x;
    int d = (i < NN) ? g_deg[i] : 0;
    sm[t] = d;
    __syncthreads();
    for (int off = 1; off < 256; off <<= 1) {
        int u = (t >= off) ? sm[t - off] : 0;
        __syncthreads();
        sm[t] += u;
        __syncthreads();
    }
    if (i < NN) {
        g_off[i] = g_bsum[blockIdx.x] + sm[t] - d;   // exclusive
        g_dinv1[i] = rsqrtf((float)d + 1.0f);
        g_dinv2[i] = rsqrtf((float)d + 2.0f);
        g_cursor[i] = 0;
    }
}

// -------- K_csrpack: fused [CSR fill | XH pack] --------
#define CSR_BLKS (EE / 256)                 // 1250
#define PACK_BLKS 2500
__global__ __launch_bounds__(256) void k_csrpack(
    const int* __restrict__ ei, const float* __restrict__ X, const float* __restrict__ H) {
    int bid = blockIdx.x, tid = threadIdx.x;
    if (bid < CSR_BLKS) {
        int e = bid * 256 + tid;
        if (e < EE) {
            int s = ei[e], d = ei[EE + e];
            int pos = atomicAdd(&g_cursor[d], 1);
            g_csr[g_off[d] + pos] = s;
        }
    } else {
        float invgn = rsqrtf(g_sumsq * (1.0f / (float)(ROWS * CIN)));
        const int total = NN * 48;
        for (int i = (bid - CSR_BLKS) * 256 + tid; i < total; i += PACK_BLKS * 256) {
            int n = i / 48, c = i % 48;
            int b = c / 12, fc = c % 12;
            float4 a, bb;
            if (fc < 4) {
                const float* xp = X + ((size_t)b * NN + n) * CIN + fc * 8;
                a = *(const float4*)xp;
                bb = *(const float4*)(xp + 4);
                a.x *= invgn; a.y *= invgn; a.z *= invgn; a.w *= invgn;
                bb.x *= invgn; bb.y *= invgn; bb.z *= invgn; bb.w *= invgn;
            } else {
                const float* hp = H + ((size_t)b * NN + n) * HID + (fc - 4) * 8;
                a = *(const float4*)hp;
                bb = *(const float4*)(hp + 4);
            }
            __half2 h0 = __floats2half2_rn(a.x, a.y);
            __half2 h1 = __floats2half2_rn(a.z, a.w);
            __half2 h2 = __floats2half2_rn(bb.x, bb.y);
            __half2 h3 = __floats2half2_rn(bb.z, bb.w);
            uint4 o;
            o.x = *(unsigned*)&h0; o.y = *(unsigned*)&h1;
            o.z = *(unsigned*)&h2; o.w = *(unsigned*)&h3;
            *(uint4*)(g_XH + (size_t)n * (BB * XHC) + c * 8) = o;
        }
    }
}

// accumulate 8 halves (one uint4) scaled by nm into a[8]
__device__ __forceinline__ void acc8(float* a, uint4 raw, float nm) {
    __half2 h0 = *(__half2*)&raw.x, h1 = *(__half2*)&raw.y;
    __half2 h2 = *(__half2*)&raw.z, h3 = *(__half2*)&raw.w;
    float2 f0 = __half22float2(h0), f1 = __half22float2(h1);
    float2 f2 = __half22float2(h2), f3 = __half22float2(h3);
    a[0] = fmaf(f0.x, nm, a[0]); a[1] = fmaf(f0.y, nm, a[1]);
    a[2] = fmaf(f1.x, nm, a[2]); a[3] = fmaf(f1.y, nm, a[3]);
    a[4] = fmaf(f2.x, nm, a[4]); a[5] = fmaf(f2.y, nm, a[5]);
    a[6] = fmaf(f3.x, nm, a[6]); a[7] = fmaf(f3.y, nm, a[7]);
}

// -------- K_aggxh: U = agg(XH) + 2*dinv2^2*XH, warp per node (fill=2) --------
__global__ __launch_bounds__(256) void k_aggxh() {
    int tid = threadIdx.x;
    int wid = tid >> 5, lane = tid & 31;
    int n = blockIdx.x * 8 + wid;
    if (n >= NN) return;

    int e0 = g_off[n], e1 = g_off[n + 1];
    float di = g_dinv2[n];
    bool active = lane < 24;
    int cA = lane, cB = lane + 24;

    float a[16];
#pragma unroll
    for (int c = 0; c < 16; c++) a[c] = 0.f;

    for (int e = e0; e < e1; e++) {
        int s = g_csr[e];
        float nm = di * g_dinv2[s];
        if (active) {
            const uint4* base = (const uint4*)(g_XH + (size_t)s * (BB * XHC));
            uint4 r0 = base[cA];
            uint4 r1 = base[cB];
            acc8(a, r0, nm);
            acc8(a + 8, r1, nm);
        }
    }
    if (active) {
        float sw = 2.0f * di * di;
        const uint4* base = (const uint4*)(g_XH + (size_t)n * (BB * XHC));
        acc8(a, base[cA], sw);
        acc8(a + 8, base[cB], sw);

        __half* up = g_U + (size_t)n * (BB * XHC);
        __half2 h0 = __floats2half2_rn(a[0], a[1]);
        __half2 h1 = __floats2half2_rn(a[2], a[3]);
        __half2 h2 = __floats2half2_rn(a[4], a[5]);
        __half2 h3 = __floats2half2_rn(a[6], a[7]);
        uint4 o0; o0.x = *(unsigned*)&h0; o0.y = *(unsigned*)&h1;
        o0.z = *(unsigned*)&h2; o0.w = *(unsigned*)&h3;
        ((uint4*)up)[cA] = o0;
        __half2 h4 = __floats2half2_rn(a[8], a[9]);
        __half2 h5 = __floats2half2_rn(a[10], a[11]);
        __half2 h6 = __floats2half2_rn(a[12], a[13]);
        __half2 h7 = __floats2half2_rn(a[14], a[15]);
        uint4 o1; o1.x = *(unsigned*)&h4; o1.y = *(unsigned*)&h5;
        o1.z = *(unsigned*)&h6; o1.w = *(unsigned*)&h7;
        ((uint4*)up)[cB] = o1;
    }
}

// -------- K_mma_gates: Z-tile = U @ Wt^T (HMMA), then gates + Hn@Wo in-block --------
__device__ __forceinline__ void mma16816(float* c, unsigned a0, unsigned a1,
                                         unsigned a2, unsigned a3,
                                         unsigned b0, unsigned b1) {
    asm volatile(
        "mma.sync.aligned.m16n8k16.row.col.f32.f16.f16.f32 "
        "{%0,%1,%2,%3}, {%4,%5,%6,%7}, {%8,%9}, {%0,%1,%2,%3};"
        : "+f"(c[0]), "+f"(c[1]), "+f"(c[2]), "+f"(c[3])
        : "r"(a0), "r"(a1), "r"(a2), "r"(a3), "r"(b0), "r"(b1));
}

#define SMEM_REGION_A_HALVES (ZC * GM_PAD + 64 * GM_PAD)   // sW + sA = 33280 halves
#define SMEM_FLOATS (HID * CIN + ZC + 3 * HID + 8 * HID)   // Wos + gb + peep + hn = 3008
#define MMA_SMEM_BYTES (SMEM_REGION_A_HALVES * 2 + SMEM_FLOATS * 4)  // 78592

__global__ __launch_bounds__(256) void k_mma_gates(
    const float* __restrict__ Cst,
    const float* __restrict__ wci, const float* __restrict__ wcf, const float* __restrict__ wco,
    const float* __restrict__ Wo) {
    extern __shared__ char smraw[];
    __half* sW = (__half*)smraw;                         // 256 x GM_PAD
    __half* sA = sW + ZC * GM_PAD;                       // 64 x GM_PAD
    __half* sZ = (__half*)smraw;                         // 64 x ZPAD, ALIASES sW/sA
    float* Wos  = (float*)(smraw + SMEM_REGION_A_HALVES * 2);  // 64x32
    float* gb   = Wos + HID * CIN;                       // 256
    float* peep = gb + ZC;                               // 192: [wci|wcf|wco]
    float* hnS  = peep + 3 * HID;                        // 8x64

    int tid = threadIdx.x;
    int wid = tid >> 5, lane = tid & 31;
    int row0 = blockIdx.x * 64;

    // load Wt (256 x 96) -> sW
    for (int i = tid; i < ZC * 12; i += 256) {
        int nn = i / 12, c = i % 12;
        uint4 v = *(const uint4*)(g_Wt + nn * XHC + c * 8);
        *(uint4*)(sW + nn * GM_PAD + c * 8) = v;
    }
    // load A tile (64 x 96) -> sA
    for (int i = tid; i < 64 * 12; i += 256) {
        int r = i / 12, c = i % 12;
        uint4 v = *(const uint4*)(g_U + (size_t)(row0 + r) * XHC + c * 8);
        *(uint4*)(sA + r * GM_PAD + c * 8) = v;
    }
    // load small tables
    for (int i = tid; i < HID * CIN; i += 256) Wos[i] = Wo[i];
    if (tid < ZC) gb[tid] = g_gbias[tid];
    if (tid < HID) {
        peep[tid] = wci[tid];
        peep[HID + tid] = wcf[tid];
        peep[2 * HID + tid] = wco[tid];
    }
    __syncthreads();

    int warpRow = wid >> 1;      // 0..3 -> 16-row slab
    int warpCol = wid & 1;       // 0..1 -> 128-col slab
    int g = lane >> 2, tg = lane & 3;

    float acc[16][4];
#pragma unroll
    for (int j = 0; j < 16; j++)
#pragma unroll
        for (int q = 0; q < 4; q++) acc[j][q] = 0.f;

#pragma unroll
    for (int kt = 0; kt < 6; kt++) {
        int karow = kt * 16 + tg * 2;
        const __half* ar = sA + (warpRow * 16 + g) * GM_PAD;
        unsigned a0 = *(const unsigned*)(ar + karow);
        unsigned a1 = *(const unsigned*)(ar + 8 * GM_PAD + karow);
        unsigned a2 = *(const unsigned*)(ar + karow + 8);
        unsigned a3 = *(const unsigned*)(ar + 8 * GM_PAD + karow + 8);
#pragma unroll
        for (int j = 0; j < 16; j++) {
            int nn = warpCol * 128 + j * 8 + g;
            const __half* bp = sW + nn * GM_PAD + karow;
            unsigned b0 = *(const unsigned*)bp;
            unsigned b1 = *(const unsigned*)(bp + 8);
            mma16816(acc[j], a0, a1, a2, a3, b0, b1);
        }
    }

    // all warps done reading sW/sA before sZ overwrites them
    __syncthreads();

    // epilogue: acc -> sZ (fp16)
    {
        int r_l = warpRow * 16 + g;
#pragma unroll
        for (int j = 0; j < 16; j++) {
            int nn = warpCol * 128 + j * 8 + tg * 2;
            __half2 h01 = __floats2half2_rn(acc[j][0], acc[j][1]);
            *(__half2*)(sZ + r_l * ZPAD + nn) = h01;
            __half2 h23 = __floats2half2_rn(acc[j][2], acc[j][3]);
            *(__half2*)(sZ + (r_l + 8) * ZPAD + nn) = h23;
        }
    }
    __syncthreads();

    // gates phase: warp wid handles rows wid*8 .. wid*8+7 (each row = one (n,b))
    for (int rr = 0; rr < 8; rr++) {
        int wl = wid * 8 + rr;
        int w = row0 + wl;
        int n = w >> 2, b = w & 3;
        const __half* z = sZ + wl * ZPAD;

        float pi0 = __half2float(z[lane])       + gb[lane];
        float pi1 = __half2float(z[lane + 32])  + gb[lane + 32];
        float pf0 = __half2float(z[64 + lane])  + gb[64 + lane];
        float pf1 = __half2float(z[96 + lane])  + gb[96 + lane];
        float pc0 = __half2float(z[128 + lane]) + gb[128 + lane];
        float pc1 = __half2float(z[160 + lane]) + gb[160 + lane];
        float po0 = __half2float(z[192 + lane]) + gb[192 + lane];
        float po1 = __half2float(z[224 + lane]) + gb[224 + lane];

        const float* cp = Cst + ((size_t)b * NN + n) * HID;
        float c0 = cp[lane], c1 = cp[lane + 32];

        float I0 = sigf(pi0 + peep[lane] * c0);
        float I1 = sigf(pi1 + peep[lane + 32] * c1);
        float F0 = sigf(pf0 + peep[HID + lane] * c0);
        float F1 = sigf(pf1 + peep[HID + lane + 32] * c1);
        float T0 = tanh_ap(pc0), T1 = tanh_ap(pc1);
        float Cn0 = F0 * c0 + I0 * T0;
        float Cn1 = F1 * c1 + I1 * T1;
        float O0 = sigf(po0 + peep[2 * HID + lane] * Cn0);
        float O1 = sigf(po1 + peep[2 * HID + lane + 32] * Cn1);
        hnS[wid * HID + lane]      = O0 * tanh_ap(Cn0);
        hnS[wid * HID + lane + 32] = O1 * tanh_ap(Cn1);
        __syncwarp();

        float y = 0.f;
#pragma unroll 16
        for (int i = 0; i < HID; i++) y = fmaf(hnS[wid * HID + i], Wos[i * CIN + lane], y);
        g_Y[(size_t)w * CIN + lane] = __float2half_rn(y);
        __syncwarp();
    }
}

// -------- K_out: output GCN (fill=1), warp per node, dual-edge lanes --------
__global__ __launch_bounds__(256) void k_out(float* __restrict__ out, const float* __restrict__ bo) {
    __shared__ float bos[CIN];
    int tid = threadIdx.x;
    if (tid < CIN) bos[tid] = bo[tid];
    __syncthreads();

    int wid = tid >> 5, lane = tid & 31;
    int n = blockIdx.x * 8 + wid;
    if (n >= NN) return;

    int e0 = g_off[n], e1 = g_off[n + 1];
    float di = g_dinv1[n];
    int half_ = lane >> 4;
    int chunk = lane & 15;            // b = chunk>>2, cols = (chunk&3)*8

    float a[8];
#pragma unroll
    for (int c = 0; c < 8; c++) a[c] = 0.f;

    for (int e = e0; e < e1; e += 2) {
        int idx = e + half_;
        if (idx < e1) {
            int s = g_csr[idx];
            float nm = di * g_dinv1[s];
            uint4 r = ((const uint4*)(g_Y + (size_t)s * (BB * CIN)))[chunk];
            acc8(a, r, nm);
        }
    }
#pragma unroll
    for (int c = 0; c < 8; c++) a[c] += __shfl_down_sync(0xffffffffu, a[c], 16);

    if (lane < 16) {
        uint4 r = ((const uint4*)(g_Y + (size_t)n * (BB * CIN)))[chunk];
        acc8(a, r, di * di);          // fill = 1 self term

        int b = chunk >> 2, colc = (chunk & 3) * 8;
        float* op = out + ((size_t)b * NN + n) * CIN + colc;
        float4 o0 = {a[0] + bos[colc + 0], a[1] + bos[colc + 1],
                     a[2] + bos[colc + 2], a[3] + bos[colc + 3]};
        float4 o1 = {a[4] + bos[colc + 4], a[5] + bos[colc + 5],
                     a[6] + bos[colc + 6], a[7] + bos[colc + 7]};
        *(float4*)op = o0;
        *(float4*)(op + 4) = o1;
    }
}

extern "C" void kernel_launch(void* const* d_in, const int* in_sizes, int n_in,
                              void* d_out, int out_size) {
    const float* X   = (const float*)d_in[0];
    const float* H   = (const float*)d_in[1];
    const float* Cst = (const float*)d_in[2];
    const int*   ei  = (const int*)d_in[3];
    const float* Wxi = (const float*)d_in[4];
    const float* bxi = (const float*)d_in[5];
    const float* Whi = (const float*)d_in[6];
    const float* bhi = (const float*)d_in[7];
    const float* Wxf = (const float*)d_in[8];
    const float* bxf = (const float*)d_in[9];
    const float* Whf = (const float*)d_in[10];
    const float* bhf = (const float*)d_in[11];
    const float* Wxc = (const float*)d_in[12];
    const float* bxc = (const float*)d_in[13];
    const float* Whc = (const float*)d_in[14];
    const float* bhc = (const float*)d_in[15];
    const float* Wxo = (const float*)d_in[16];
    const float* bxo = (const float*)d_in[17];
    const float* Who = (const float*)d_in[18];
    const float* bho = (const float*)d_in[19];
    const float* wci = (const float*)d_in[20];
    const float* wcf = (const float*)d_in[21];
    const float* wco = (const float*)d_in[22];
    const float* bi  = (const float*)d_in[23];
    const float* bf  = (const float*)d_in[24];
    const float* bc  = (const float*)d_in[25];
    const float* bo_ = (const float*)d_in[26];
    const float* Wo  = (const float*)d_in[27];
    const float* bo2 = (const float*)d_in[28];
    float* out = (float*)d_out;

    cudaFuncSetAttribute(k_mma_gates, cudaFuncAttributeMaxDynamicSharedMemorySize,
                         MMA_SMEM_BYTES);

    // zero the small accumulators (scratch tensors are fully overwritten)
    void *p_sumsq, *p_deg;
    cudaGetSymbolAddress(&p_sumsq, g_sumsq);
    cudaGetSymbolAddress(&p_deg, g_deg);
    cudaMemsetAsync(p_sumsq, 0, sizeof(float));
    cudaMemsetAsync(p_deg, 0, NN * sizeof(int));

    k_setup<<<SETUP_GRID, 256>>>(X, ei,
                                 Wxi, Wxf, Wxc, Wxo, Whi, Whf, Whc, Who,
                                 bxi, bxf, bxc, bxo, bhi, bhf, bhc, bho,
                                 bi, bf, bc, bo_);
    k_scan_a<<<SCAN_GRID, 256>>>();
    k_scan_b<<<1, 128>>>();
    k_scan_c<<<SCAN_GRID, 256>>>();
    k_csrpack<<<CSR_BLKS + PACK_BLKS, 256>>>(ei, X, H);
    k_aggxh<<<(NN + 7) / 8, 256>>>();
    k_mma_gates<<<ROWS / 64, 256, MMA_SMEM_BYTES>>>(Cst, wci, wcf, wco, Wo);
    k_out<<<(NN + 7) / 8, 256>>>(out, bo2);
}